// round 4
// baseline (speedup 1.0000x reference)
#include <cuda_runtime.h>
#include <cuda_bf16.h>

// Problem constants
#define Nn    50000
#define Dd    128
#define Rr    10
#define Ee    800000
#define NSEL  8192
#define NCc   12
#define EPAD  (Ee + Rr * 128)
#define TILES_MAX ((Ee / 128) + Rr)

// ---------------- device scratch (static allocations only) ----------------
__device__ float g_x[Nn * Dd];          // node features (tf32-rounded)
__device__ float g_acc[Nn * Dd];        // conv accumulator (fp32)
__device__ float g_W[Rr * Dd * Dd];     // relation weights (tf32-rounded)
__device__ int   g_icnt[Rr * Nn];       // per-(r,dst) edge counts
__device__ float g_inv[Rr * Nn];        // 1/max(cnt,1)
__device__ float g_hsel[NSEL * Dd];     // classifier hidden
__device__ int   g_rcnt[Rr];            // per-relation edge counts
__device__ int   g_cur[Rr];             // placement cursors
__device__ int   g_toff[Rr + 1];        // tile offsets (prefix of ceil(cnt/128))
__device__ int   g_esrc[EPAD];          // sorted edge src
__device__ int   g_edst[EPAD];          // sorted edge dst
__device__ float g_ew[EPAD];            // sorted edge weight (inv), 0 for pads

// ---------------- helpers ----------------
__device__ __forceinline__ unsigned f2tf(float f) {
    unsigned u;
    asm("cvt.rna.tf32.f32 %0, %1;" : "=r"(u) : "f"(f));
    return u;
}
__device__ __forceinline__ float tf32r(float f) { return __uint_as_float(f2tf(f)); }

__device__ __forceinline__ void mma_tf32(float c[4], const unsigned a[4], const unsigned b[2]) {
    asm volatile("mma.sync.aligned.m16n8k8.row.col.f32.tf32.tf32.f32 "
                 "{%0,%1,%2,%3}, {%4,%5,%6,%7}, {%8,%9}, {%0,%1,%2,%3};"
                 : "+f"(c[0]), "+f"(c[1]), "+f"(c[2]), "+f"(c[3])
                 : "r"(a[0]), "r"(a[1]), "r"(a[2]), "r"(a[3]), "r"(b[0]), "r"(b[1]));
}

// ---------------- small kernels ----------------
__global__ void k_copy_x(const float* __restrict__ src) {
    int i = blockIdx.x * blockDim.x + threadIdx.x;
    if (i >= Nn * Dd / 4) return;
    float4 v = ((const float4*)src)[i];
    v.x = tf32r(v.x); v.y = tf32r(v.y); v.z = tf32r(v.z); v.w = tf32r(v.w);
    ((float4*)g_x)[i] = v;
}

__global__ void k_build_W(const float* __restrict__ comp, const float* __restrict__ bases) {
    int i = blockIdx.x * blockDim.x + threadIdx.x;
    if (i >= Rr * Dd * Dd) return;
    int slot = i >> 14;
    int idx  = i & 16383;
    float v = 0.f;
#pragma unroll
    for (int b = 0; b < 4; b++)
        v += comp[slot * 4 + b] * bases[b * Dd * Dd + idx];
    g_W[i] = tf32r(v);
}

__global__ void k_zero_cnt() {
    int i = blockIdx.x * blockDim.x + threadIdx.x;
    if (i < Rr * Nn) g_icnt[i] = 0;
    if (i < Rr) { g_rcnt[i] = 0; g_cur[i] = 0; }
}

__global__ void k_count(const int* __restrict__ ei, const int* __restrict__ et) {
    int e = blockIdx.x * blockDim.x + threadIdx.x;
    if (e >= Ee) return;
    int r = et[e];
    atomicAdd(&g_icnt[r * Nn + ei[Ee + e]], 1);
    atomicAdd(&g_rcnt[r], 1);
}

__global__ void k_inv() {
    int i = blockIdx.x * blockDim.x + threadIdx.x;
    if (i < Rr * Nn) g_inv[i] = 1.0f / fmaxf((float)g_icnt[i], 1.0f);
}

__global__ void k_offsets() {
    int t = 0;
    g_toff[0] = 0;
    for (int r = 0; r < Rr; r++) {
        t += (g_rcnt[r] + 127) / 128;
        g_toff[r + 1] = t;
    }
}

__global__ void k_prefill() {
    int i = blockIdx.x * blockDim.x + threadIdx.x;
    if (i >= EPAD) return;
    g_esrc[i] = 0; g_edst[i] = 0; g_ew[i] = 0.f;
}

__global__ void k_place(const int* __restrict__ ei, const int* __restrict__ et) {
    int e = blockIdx.x * blockDim.x + threadIdx.x;
    if (e >= Ee) return;
    int r = et[e];
    int pos = g_toff[r] * 128 + atomicAdd(&g_cur[r], 1);
    int s = ei[e], t = ei[Ee + e];
    g_esrc[pos] = s;
    g_edst[pos] = t;
    g_ew[pos]   = g_inv[r * Nn + t];
}

// one warp per node: LayerNorm (+optional ReLU), g_acc -> g_x (tf32-rounded)
__global__ void k_ln(const float* __restrict__ g, const float* __restrict__ b, int relu) {
    int gt = blockIdx.x * blockDim.x + threadIdx.x;
    int node = gt >> 5;
    if (node >= Nn) return;
    int lane = gt & 31;
    float4 v = ((const float4*)g_acc)[node * 32 + lane];
    float s = v.x + v.y + v.z + v.w;
    float q = v.x * v.x + v.y * v.y + v.z * v.z + v.w * v.w;
#pragma unroll
    for (int o = 16; o; o >>= 1) {
        s += __shfl_xor_sync(0xffffffffu, s, o);
        q += __shfl_xor_sync(0xffffffffu, q, o);
    }
    float mean = s * (1.f / 128.f);
    float var  = q * (1.f / 128.f) - mean * mean;
    float rstd = rsqrtf(var + 1e-5f);
    float4 gg = ((const float4*)g)[lane];
    float4 bb = ((const float4*)b)[lane];
    float4 o4;
    o4.x = (v.x - mean) * rstd * gg.x + bb.x;
    o4.y = (v.y - mean) * rstd * gg.y + bb.y;
    o4.z = (v.z - mean) * rstd * gg.z + bb.z;
    o4.w = (v.w - mean) * rstd * gg.w + bb.w;
    if (relu) {
        o4.x = fmaxf(o4.x, 0.f); o4.y = fmaxf(o4.y, 0.f);
        o4.z = fmaxf(o4.z, 0.f); o4.w = fmaxf(o4.w, 0.f);
    }
    o4.x = tf32r(o4.x); o4.y = tf32r(o4.y); o4.z = tf32r(o4.z); o4.w = tf32r(o4.w);
    ((float4*)g_x)[node * 32 + lane] = o4;
}

// final tiny GEMM
__global__ void k_final(const float* __restrict__ W, const float* __restrict__ b,
                        float* __restrict__ out) {
    int gt = blockIdx.x * blockDim.x + threadIdx.x;
    if (gt >= NSEL * NCc) return;
    int i = gt / NCc, c = gt % NCc;
    const float* hr = g_hsel + i * Dd;
    float s = b[c];
#pragma unroll 8
    for (int k = 0; k < Dd; k++) s += hr[k] * W[k * NCc + c];
    out[gt] = s;
}

// ---------------- dense tf32 GEMM (projections / root / classifier) ----------------
// C tile 128x128, 256 threads = 8 warps (4m x 2n), warp tile 32x64. N==128.
__global__ void __launch_bounds__(256)
tgemm(const float* __restrict__ A, const int* __restrict__ aIdx,
      int M, int K,
      const float* __restrict__ B,
      float* __restrict__ C,
      const float* __restrict__ bias, int relu, int tf32out,
      const int* __restrict__ rowIdx) {
    int row0 = blockIdx.x * 128;
    __shared__ unsigned As[128][36];
    __shared__ unsigned Bs[32][136];
    float acc[2][8][4];
#pragma unroll
    for (int mt = 0; mt < 2; mt++)
#pragma unroll
        for (int nt = 0; nt < 8; nt++)
#pragma unroll
            for (int q = 0; q < 4; q++) acc[mt][nt][q] = 0.f;

    int tid = threadIdx.x;
    int lane = tid & 31, wid = tid >> 5;
    int wm = (wid >> 1) * 32;
    int wn = (wid & 1) * 64;

    for (int kb = 0; kb < K; kb += 32) {
#pragma unroll
        for (int it = 0; it < 4; it++) {
            int idx = tid + it * 256;
            int m = idx >> 3;
            int kq = (idx & 7) * 4;
            float4 v = make_float4(0.f, 0.f, 0.f, 0.f);
            int row = row0 + m;
            if (row < M) {
                int ar = aIdx ? aIdx[row] : row;
                v = *(const float4*)&A[(size_t)ar * K + kb + kq];
            }
            As[m][kq + 0] = f2tf(v.x); As[m][kq + 1] = f2tf(v.y);
            As[m][kq + 2] = f2tf(v.z); As[m][kq + 3] = f2tf(v.w);
        }
#pragma unroll
        for (int it = 0; it < 4; it++) {
            int idx = tid + it * 256;
            int k = idx >> 5;
            int nq = (idx & 31) * 4;
            float4 v = *(const float4*)&B[(size_t)(kb + k) * 128 + nq];
            Bs[k][nq + 0] = f2tf(v.x); Bs[k][nq + 1] = f2tf(v.y);
            Bs[k][nq + 2] = f2tf(v.z); Bs[k][nq + 3] = f2tf(v.w);
        }
        __syncthreads();
#pragma unroll
        for (int ks = 0; ks < 4; ks++) {
            int k0 = ks * 8;
            unsigned af[2][4];
#pragma unroll
            for (int mt = 0; mt < 2; mt++) {
                int r = wm + mt * 16 + (lane >> 2);
                int c = k0 + (lane & 3);
                af[mt][0] = As[r][c];     af[mt][1] = As[r + 8][c];
                af[mt][2] = As[r][c + 4]; af[mt][3] = As[r + 8][c + 4];
            }
#pragma unroll
            for (int nt = 0; nt < 8; nt++) {
                unsigned bf[2];
                int br = k0 + (lane & 3);
                int bc = wn + nt * 8 + (lane >> 2);
                bf[0] = Bs[br][bc];
                bf[1] = Bs[br + 4][bc];
                mma_tf32(acc[0][nt], af[0], bf);
                mma_tf32(acc[1][nt], af[1], bf);
            }
        }
        __syncthreads();
    }

#pragma unroll
    for (int mt = 0; mt < 2; mt++) {
#pragma unroll
        for (int h = 0; h < 2; h++) {
            int row = row0 + wm + mt * 16 + (lane >> 2) + h * 8;
            if (row >= M) continue;
            int cr = rowIdx ? rowIdx[row] : row;
#pragma unroll
            for (int nt = 0; nt < 8; nt++) {
                int col = wn + nt * 8 + 2 * (lane & 3);
                float v0 = acc[mt][nt][h * 2 + 0];
                float v1 = acc[mt][nt][h * 2 + 1];
                if (bias) { v0 += bias[col]; v1 += bias[col + 1]; }
                if (relu) { v0 = fmaxf(v0, 0.f); v1 = fmaxf(v1, 0.f); }
                if (tf32out) { v0 = tf32r(v0); v1 = tf32r(v1); }
                *(float2*)&C[(size_t)cr * 128 + col] = make_float2(v0, v1);
            }
        }
    }
}

// ---------------- fused edge GEMM: gather x[src] -> @W[r] -> scaled red.add to acc ----
// One block per 128-edge tile of the relation-sorted edge list. x and W pre-tf32.
__global__ void __launch_bounds__(256)
egemm() {
    int t = blockIdx.x;
    if (t >= g_toff[Rr]) return;
    int r = 0;
    while (t >= g_toff[r + 1]) r++;
    int base = t * 128;

    __shared__ unsigned As[128][36];
    __shared__ unsigned Bs[32][136];

    float acc[2][8][4];
#pragma unroll
    for (int mt = 0; mt < 2; mt++)
#pragma unroll
        for (int nt = 0; nt < 8; nt++)
#pragma unroll
            for (int q = 0; q < 4; q++) acc[mt][nt][q] = 0.f;

    int tid = threadIdx.x;
    int lane = tid & 31, wid = tid >> 5;
    int wm = (wid >> 1) * 32;
    int wn = (wid & 1) * 64;

    // gather row indices once (each thread loads 4 rows per k-block, same rows every block)
    int srcs[4];
#pragma unroll
    for (int it = 0; it < 4; it++) {
        int m = (tid + it * 256) >> 3;
        srcs[it] = g_esrc[base + m];
    }
    const float* Wz = g_W + r * (Dd * Dd);

    for (int kb = 0; kb < 128; kb += 32) {
#pragma unroll
        for (int it = 0; it < 4; it++) {
            int idx = tid + it * 256;
            int m = idx >> 3;
            int kq = (idx & 7) * 4;
            float4 v = *(const float4*)&g_x[(size_t)srcs[it] * 128 + kb + kq];
            As[m][kq + 0] = __float_as_uint(v.x); As[m][kq + 1] = __float_as_uint(v.y);
            As[m][kq + 2] = __float_as_uint(v.z); As[m][kq + 3] = __float_as_uint(v.w);
        }
#pragma unroll
        for (int it = 0; it < 4; it++) {
            int idx = tid + it * 256;
            int k = idx >> 5;
            int nq = (idx & 31) * 4;
            float4 v = *(const float4*)&Wz[(size_t)(kb + k) * 128 + nq];
            Bs[k][nq + 0] = __float_as_uint(v.x); Bs[k][nq + 1] = __float_as_uint(v.y);
            Bs[k][nq + 2] = __float_as_uint(v.z); Bs[k][nq + 3] = __float_as_uint(v.w);
        }
        __syncthreads();
#pragma unroll
        for (int ks = 0; ks < 4; ks++) {
            int k0 = ks * 8;
            unsigned af[2][4];
#pragma unroll
            for (int mt = 0; mt < 2; mt++) {
                int rr = wm + mt * 16 + (lane >> 2);
                int cc = k0 + (lane & 3);
                af[mt][0] = As[rr][cc];     af[mt][1] = As[rr + 8][cc];
                af[mt][2] = As[rr][cc + 4]; af[mt][3] = As[rr + 8][cc + 4];
            }
#pragma unroll
            for (int nt = 0; nt < 8; nt++) {
                unsigned bf[2];
                int br = k0 + (lane & 3);
                int bc = wn + nt * 8 + (lane >> 2);
                bf[0] = Bs[br][bc];
                bf[1] = Bs[br + 4][bc];
                mma_tf32(acc[0][nt], af[0], bf);
                mma_tf32(acc[1][nt], af[1], bf);
            }
        }
        __syncthreads();
    }

    // epilogue: scale row by edge weight, red.add into acc[dst]
#pragma unroll
    for (int mt = 0; mt < 2; mt++) {
#pragma unroll
        for (int h = 0; h < 2; h++) {
            int row = base + wm + mt * 16 + (lane >> 2) + h * 8;
            int dst = g_edst[row];
            float w = g_ew[row];
            float* outr = g_acc + (size_t)dst * 128;
#pragma unroll
            for (int nt = 0; nt < 8; nt++) {
                int col = wn + nt * 8 + 2 * (lane & 3);
                float v0 = acc[mt][nt][h * 2 + 0] * w;
                float v1 = acc[mt][nt][h * 2 + 1] * w;
                asm volatile("red.global.add.v2.f32 [%0], {%1,%2};"
                             :: "l"(outr + col), "f"(v0), "f"(v1) : "memory");
            }
        }
    }
}

// ---------------- launch ----------------
extern "C" void kernel_launch(void* const* d_in, const int* in_sizes, int n_in,
                              void* d_out, int out_size) {
    const int*   edge_index   = (const int*)d_in[0];
    const int*   edge_type    = (const int*)d_in[1];
    const int*   node_indices = (const int*)d_in[2];
    const float* file_feats   = (const float*)d_in[3];
    const int*   file_idx     = (const int*)d_in[4];
    const float* domain_feats = (const float*)d_in[5];
    const int*   domain_idx   = (const int*)d_in[6];
    const float* ip_feats     = (const float*)d_in[7];
    const int*   ip_idx       = (const int*)d_in[8];
    const float* fallback     = (const float*)d_in[9];
    const float* Wf  = (const float*)d_in[10];
    const float* bf  = (const float*)d_in[11];
    const float* Wd  = (const float*)d_in[12];
    const float* bd  = (const float*)d_in[13];
    const float* Wi  = (const float*)d_in[14];
    const float* bi  = (const float*)d_in[15];
    const float* comp1  = (const float*)d_in[16];
    const float* bases1 = (const float*)d_in[17];
    const float* root1  = (const float*)d_in[18];
    const float* bias1  = (const float*)d_in[19];
    const float* comp2  = (const float*)d_in[20];
    const float* bases2 = (const float*)d_in[21];
    const float* root2  = (const float*)d_in[22];
    const float* bias2  = (const float*)d_in[23];
    const float* ln1_g  = (const float*)d_in[24];
    const float* ln1_b  = (const float*)d_in[25];
    const float* ln2_g  = (const float*)d_in[26];
    const float* ln2_b  = (const float*)d_in[27];
    const float* Wc1 = (const float*)d_in[28];
    const float* bc1 = (const float*)d_in[29];
    const float* Wc2 = (const float*)d_in[30];
    const float* bc2 = (const float*)d_in[31];
    float* out = (float*)d_out;

    float *px, *pacc, *phsel;
    cudaGetSymbolAddress((void**)&px,    g_x);
    cudaGetSymbolAddress((void**)&pacc,  g_acc);
    cudaGetSymbolAddress((void**)&phsel, g_hsel);

    // ---- build node features (tf32-rounded into g_x) ----
    k_copy_x<<<(Nn * Dd / 4 + 255) / 256, 256>>>(fallback);
    tgemm<<<157, 256>>>(file_feats,   nullptr, 20000, 256, Wf, px, bf, 0, 1, file_idx);
    tgemm<<<118, 256>>>(domain_feats, nullptr, 15000, 128, Wd, px, bd, 0, 1, domain_idx);
    tgemm<<<79,  256>>>(ip_feats,     nullptr, 10000, 64,  Wi, px, bi, 0, 1, ip_idx);

    // ---- edge counts + relation sort (layer-independent, weights reused) ----
    k_zero_cnt<<<(Rr * Nn + 255) / 256, 256>>>();
    k_count<<<(Ee + 255) / 256, 256>>>(edge_index, edge_type);
    k_inv<<<(Rr * Nn + 255) / 256, 256>>>();
    k_offsets<<<1, 1>>>();
    k_prefill<<<(EPAD + 255) / 256, 256>>>();
    k_place<<<(Ee + 255) / 256, 256>>>(edge_index, edge_type);

    int gemmRows = (Nn + 127) / 128;  // 391

    // ---- layer 1 ----
    k_build_W<<<(Rr * Dd * Dd + 255) / 256, 256>>>(comp1, bases1);
    tgemm<<<gemmRows, 256>>>(px, nullptr, Nn, 128, root1, pacc, bias1, 0, 0, nullptr);
    egemm<<<TILES_MAX, 256>>>();
    k_ln<<<(Nn * 32 + 255) / 256, 256>>>(ln1_g, ln1_b, 1);

    // ---- layer 2 ----
    k_build_W<<<(Rr * Dd * Dd + 255) / 256, 256>>>(comp2, bases2);
    tgemm<<<gemmRows, 256>>>(px, nullptr, Nn, 128, root2, pacc, bias2, 0, 0, nullptr);
    egemm<<<TILES_MAX, 256>>>();
    k_ln<<<(Nn * 32 + 255) / 256, 256>>>(ln2_g, ln2_b, 0);

    // ---- classifier ----
    tgemm<<<(NSEL + 127) / 128, 256>>>(px, node_indices, NSEL, 128, Wc1,
                                       phsel, bc1, 1, 0, nullptr);
    k_final<<<(NSEL * NCc + 255) / 256, 256>>>(Wc2, bc2, out);
}

// round 5
// speedup vs baseline: 1.5925x; 1.5925x over previous
#include <cuda_runtime.h>
#include <cuda_bf16.h>

// Problem constants
#define Nn    50000
#define Dd    128
#define Rr    10
#define Ee    800000
#define NSEL  8192
#define NCc   12
#define NTILE 391                 // ceil(Nn/128)
#define NG    782                 // ceil(Nn/64) src groups
#define NBKT  (Rr * NG)           // 7820 buckets

// ---------------- device scratch (static allocations only) ----------------
__device__ float g_x[Nn * Dd];          // node features (tf32-rounded)
__device__ float g_acc[Nn * Dd];        // conv accumulator (fp32)
__device__ float g_W[Rr * Dd * Dd];     // relation weights (tf32-rounded)
__device__ int   g_icnt[Rr * Nn];       // per-(r,dst) edge counts
__device__ float g_inv[Rr * Nn];        // 1/max(cnt,1)
__device__ float g_hsel[NSEL * Dd];     // classifier hidden
__device__ int   g_bcnt[NBKT];          // bucket counts
__device__ int   g_bcur[NBKT];          // bucket cursors
__device__ int   g_boff[NBKT + 1];      // bucket offsets
__device__ int   g_bsrc[Ee];            // bucketed edge src
__device__ int   g_bdst[Ee];            // bucketed edge dst
__device__ float g_bw[Ee];              // bucketed edge weight inv[r,dst]

// ---------------- helpers ----------------
__device__ __forceinline__ unsigned f2tf(float f) {
    unsigned u;
    asm("cvt.rna.tf32.f32 %0, %1;" : "=r"(u) : "f"(f));
    return u;
}
__device__ __forceinline__ float tf32r(float f) { return __uint_as_float(f2tf(f)); }

__device__ __forceinline__ void mma_tf32(float c[4], const unsigned a[4], const unsigned b[2]) {
    asm volatile("mma.sync.aligned.m16n8k8.row.col.f32.tf32.tf32.f32 "
                 "{%0,%1,%2,%3}, {%4,%5,%6,%7}, {%8,%9}, {%0,%1,%2,%3};"
                 : "+f"(c[0]), "+f"(c[1]), "+f"(c[2]), "+f"(c[3])
                 : "r"(a[0]), "r"(a[1]), "r"(a[2]), "r"(a[3]), "r"(b[0]), "r"(b[1]));
}

// ---------------- small kernels ----------------
__global__ void k_copy_x(const float* __restrict__ src) {
    int i = blockIdx.x * blockDim.x + threadIdx.x;
    if (i >= Nn * Dd / 4) return;
    float4 v = ((const float4*)src)[i];
    v.x = tf32r(v.x); v.y = tf32r(v.y); v.z = tf32r(v.z); v.w = tf32r(v.w);
    ((float4*)g_x)[i] = v;
}

__global__ void k_build_W(const float* __restrict__ comp, const float* __restrict__ bases) {
    int i = blockIdx.x * blockDim.x + threadIdx.x;
    if (i >= Rr * Dd * Dd) return;
    int slot = i >> 14;
    int idx  = i & 16383;
    float v = 0.f;
#pragma unroll
    for (int b = 0; b < 4; b++)
        v += comp[slot * 4 + b] * bases[b * Dd * Dd + idx];
    g_W[i] = tf32r(v);
}

__global__ void k_zero_cnt() {
    int i = blockIdx.x * blockDim.x + threadIdx.x;
    if (i < Rr * Nn) g_icnt[i] = 0;
    if (i < NBKT) { g_bcnt[i] = 0; g_bcur[i] = 0; }
}

__global__ void k_count(const int* __restrict__ ei, const int* __restrict__ et) {
    int e = blockIdx.x * blockDim.x + threadIdx.x;
    if (e >= Ee) return;
    int r = et[e];
    atomicAdd(&g_icnt[r * Nn + ei[Ee + e]], 1);
    atomicAdd(&g_bcnt[r * NG + (ei[e] >> 6)], 1);
}

__global__ void k_inv() {
    int i = blockIdx.x * blockDim.x + threadIdx.x;
    if (i < Rr * Nn) g_inv[i] = 1.0f / fmaxf((float)g_icnt[i], 1.0f);
}

// single-block scan over NBKT bucket counts -> g_boff
__global__ void k_scan() {
    __shared__ int part[1024];
    int t = threadIdx.x;
    int s = 0;
#pragma unroll
    for (int j = 0; j < 8; j++) {
        int b = t * 8 + j;
        if (b < NBKT) s += g_bcnt[b];
    }
    part[t] = s;
    __syncthreads();
    for (int o = 1; o < 1024; o <<= 1) {
        int v = (t >= o) ? part[t - o] : 0;
        __syncthreads();
        part[t] += v;
        __syncthreads();
    }
    int run = (t > 0) ? part[t - 1] : 0;
#pragma unroll
    for (int j = 0; j < 8; j++) {
        int b = t * 8 + j;
        if (b < NBKT) { g_boff[b] = run; run += g_bcnt[b]; }
    }
    if (t == 0) g_boff[NBKT] = part[1023];
}

__global__ void k_place(const int* __restrict__ ei, const int* __restrict__ et) {
    int e = blockIdx.x * blockDim.x + threadIdx.x;
    if (e >= Ee) return;
    int r = et[e];
    int s = ei[e], t = ei[Ee + e];
    int key = r * NG + (s >> 6);
    int pos = g_boff[key] + atomicAdd(&g_bcur[key], 1);
    g_bsrc[pos] = s;
    g_bdst[pos] = t;
    g_bw[pos]   = g_inv[r * Nn + t];
}

// one warp per node: LayerNorm (+optional ReLU), g_acc -> g_x (tf32-rounded)
__global__ void k_ln(const float* __restrict__ g, const float* __restrict__ b, int relu) {
    int gt = blockIdx.x * blockDim.x + threadIdx.x;
    int node = gt >> 5;
    if (node >= Nn) return;
    int lane = gt & 31;
    float4 v = ((const float4*)g_acc)[node * 32 + lane];
    float s = v.x + v.y + v.z + v.w;
    float q = v.x * v.x + v.y * v.y + v.z * v.z + v.w * v.w;
#pragma unroll
    for (int o = 16; o; o >>= 1) {
        s += __shfl_xor_sync(0xffffffffu, s, o);
        q += __shfl_xor_sync(0xffffffffu, q, o);
    }
    float mean = s * (1.f / 128.f);
    float var  = q * (1.f / 128.f) - mean * mean;
    float rstd = rsqrtf(var + 1e-5f);
    float4 gg = ((const float4*)g)[lane];
    float4 bb = ((const float4*)b)[lane];
    float4 o4;
    o4.x = (v.x - mean) * rstd * gg.x + bb.x;
    o4.y = (v.y - mean) * rstd * gg.y + bb.y;
    o4.z = (v.z - mean) * rstd * gg.z + bb.z;
    o4.w = (v.w - mean) * rstd * gg.w + bb.w;
    if (relu) {
        o4.x = fmaxf(o4.x, 0.f); o4.y = fmaxf(o4.y, 0.f);
        o4.z = fmaxf(o4.z, 0.f); o4.w = fmaxf(o4.w, 0.f);
    }
    o4.x = tf32r(o4.x); o4.y = tf32r(o4.y); o4.z = tf32r(o4.z); o4.w = tf32r(o4.w);
    ((float4*)g_x)[node * 32 + lane] = o4;
}

// final tiny GEMM
__global__ void k_final(const float* __restrict__ W, const float* __restrict__ b,
                        float* __restrict__ out) {
    int gt = blockIdx.x * blockDim.x + threadIdx.x;
    if (gt >= NSEL * NCc) return;
    int i = gt / NCc, c = gt % NCc;
    const float* hr = g_hsel + i * Dd;
    float s = b[c];
#pragma unroll 8
    for (int k = 0; k < Dd; k++) s += hr[k] * W[k * NCc + c];
    out[gt] = s;
}

// ---------------- dense tf32 GEMM (projections / root-init / classifier) --------
// C tile 128x128, 256 threads = 8 warps (4m x 2n), warp tile 32x64. N==128.
__global__ void __launch_bounds__(256)
tgemm(const float* __restrict__ A, const int* __restrict__ aIdx,
      int M, int K,
      const float* __restrict__ B,
      float* __restrict__ C,
      const float* __restrict__ bias, int relu, int tf32out,
      const int* __restrict__ rowIdx) {
    int row0 = blockIdx.x * 128;
    __shared__ unsigned As[128][36];
    __shared__ unsigned Bs[32][136];
    float acc[2][8][4];
#pragma unroll
    for (int mt = 0; mt < 2; mt++)
#pragma unroll
        for (int nt = 0; nt < 8; nt++)
#pragma unroll
            for (int q = 0; q < 4; q++) acc[mt][nt][q] = 0.f;

    int tid = threadIdx.x;
    int lane = tid & 31, wid = tid >> 5;
    int wm = (wid >> 1) * 32;
    int wn = (wid & 1) * 64;

    for (int kb = 0; kb < K; kb += 32) {
#pragma unroll
        for (int it = 0; it < 4; it++) {
            int idx = tid + it * 256;
            int m = idx >> 3;
            int kq = (idx & 7) * 4;
            float4 v = make_float4(0.f, 0.f, 0.f, 0.f);
            int row = row0 + m;
            if (row < M) {
                int ar = aIdx ? aIdx[row] : row;
                v = *(const float4*)&A[(size_t)ar * K + kb + kq];
            }
            As[m][kq + 0] = f2tf(v.x); As[m][kq + 1] = f2tf(v.y);
            As[m][kq + 2] = f2tf(v.z); As[m][kq + 3] = f2tf(v.w);
        }
#pragma unroll
        for (int it = 0; it < 4; it++) {
            int idx = tid + it * 256;
            int k = idx >> 5;
            int nq = (idx & 31) * 4;
            float4 v = *(const float4*)&B[(size_t)(kb + k) * 128 + nq];
            Bs[k][nq + 0] = f2tf(v.x); Bs[k][nq + 1] = f2tf(v.y);
            Bs[k][nq + 2] = f2tf(v.z); Bs[k][nq + 3] = f2tf(v.w);
        }
        __syncthreads();
#pragma unroll
        for (int ks = 0; ks < 4; ks++) {
            int k0 = ks * 8;
            unsigned af[2][4];
#pragma unroll
            for (int mt = 0; mt < 2; mt++) {
                int r = wm + mt * 16 + (lane >> 2);
                int c = k0 + (lane & 3);
                af[mt][0] = As[r][c];     af[mt][1] = As[r + 8][c];
                af[mt][2] = As[r][c + 4]; af[mt][3] = As[r + 8][c + 4];
            }
#pragma unroll
            for (int nt = 0; nt < 8; nt++) {
                unsigned bf[2];
                int br = k0 + (lane & 3);
                int bc = wn + nt * 8 + (lane >> 2);
                bf[0] = Bs[br][bc];
                bf[1] = Bs[br + 4][bc];
                mma_tf32(acc[0][nt], af[0], bf);
                mma_tf32(acc[1][nt], af[1], bf);
            }
        }
        __syncthreads();
    }

#pragma unroll
    for (int mt = 0; mt < 2; mt++) {
#pragma unroll
        for (int h = 0; h < 2; h++) {
            int row = row0 + wm + mt * 16 + (lane >> 2) + h * 8;
            if (row >= M) continue;
            int cr = rowIdx ? rowIdx[row] : row;
#pragma unroll
            for (int nt = 0; nt < 8; nt++) {
                int col = wn + nt * 8 + 2 * (lane & 3);
                float v0 = acc[mt][nt][h * 2 + 0];
                float v1 = acc[mt][nt][h * 2 + 1];
                if (bias) { v0 += bias[col]; v1 += bias[col + 1]; }
                if (relu) { v0 = fmaxf(v0, 0.f); v1 = fmaxf(v1, 0.f); }
                if (tf32out) { v0 = tf32r(v0); v1 = tf32r(v1); }
                *(float2*)&C[(size_t)cr * 128 + col] = make_float2(v0, v1);
            }
        }
    }
}

// ---------------- fused dense GEMM + edge scatter ----------------
// grid = (NTILE, Rr). Computes tile xw = x[row0:row0+128] @ W[r] (tf32 MMA),
// stages it in smem in two 64-row halves, and for each half walks the edge
// bucket (r, srcgroup) scattering w * xw[src] into g_acc[dst] via red.add.v4.
// x and W are pre-rounded to tf32 (no cvt in the hot loop).
__global__ void __launch_bounds__(256)
ftgemm() {
    __shared__ __align__(16) char smem_raw[128 * 36 * 4 + 32 * 136 * 4];
    unsigned (*As)[36]  = (unsigned(*)[36])smem_raw;
    unsigned (*Bs)[136] = (unsigned(*)[136])(smem_raw + 128 * 36 * 4);
    float (*Ch)[132]    = (float(*)[132])smem_raw;   // 64x132 = 33792 B, reuses As/Bs

    int tile = blockIdx.x;
    int r    = blockIdx.y;
    int row0 = tile * 128;

    float acc[2][8][4];
#pragma unroll
    for (int mt = 0; mt < 2; mt++)
#pragma unroll
        for (int nt = 0; nt < 8; nt++)
#pragma unroll
            for (int q = 0; q < 4; q++) acc[mt][nt][q] = 0.f;

    int tid = threadIdx.x;
    int lane = tid & 31, wid = tid >> 5;
    int wm = (wid >> 1) * 32;
    int wn = (wid & 1) * 64;

    // skip tiles with no edges in either half-bucket
    int bkt0 = r * NG + tile * 2;
    int lo0 = g_boff[bkt0], hi1 = g_boff[bkt0 + 2];
    if (lo0 == hi1) return;

    const float* Wz = g_W + r * (Dd * Dd);

    for (int kb = 0; kb < 128; kb += 32) {
#pragma unroll
        for (int it = 0; it < 4; it++) {
            int idx = tid + it * 256;
            int m = idx >> 3;
            int kq = (idx & 7) * 4;
            float4 v = make_float4(0.f, 0.f, 0.f, 0.f);
            int row = row0 + m;
            if (row < Nn) v = *(const float4*)&g_x[(size_t)row * 128 + kb + kq];
            As[m][kq + 0] = __float_as_uint(v.x); As[m][kq + 1] = __float_as_uint(v.y);
            As[m][kq + 2] = __float_as_uint(v.z); As[m][kq + 3] = __float_as_uint(v.w);
        }
#pragma unroll
        for (int it = 0; it < 4; it++) {
            int idx = tid + it * 256;
            int k = idx >> 5;
            int nq = (idx & 31) * 4;
            float4 v = *(const float4*)&Wz[(size_t)(kb + k) * 128 + nq];
            Bs[k][nq + 0] = __float_as_uint(v.x); Bs[k][nq + 1] = __float_as_uint(v.y);
            Bs[k][nq + 2] = __float_as_uint(v.z); Bs[k][nq + 3] = __float_as_uint(v.w);
        }
        __syncthreads();
#pragma unroll
        for (int ks = 0; ks < 4; ks++) {
            int k0 = ks * 8;
            unsigned af[2][4];
#pragma unroll
            for (int mt = 0; mt < 2; mt++) {
                int rr = wm + mt * 16 + (lane >> 2);
                int cc = k0 + (lane & 3);
                af[mt][0] = As[rr][cc];     af[mt][1] = As[rr + 8][cc];
                af[mt][2] = As[rr][cc + 4]; af[mt][3] = As[rr + 8][cc + 4];
            }
#pragma unroll
            for (int nt = 0; nt < 8; nt++) {
                unsigned bf[2];
                int br = k0 + (lane & 3);
                int bc = wn + nt * 8 + (lane >> 2);
                bf[0] = Bs[br][bc];
                bf[1] = Bs[br + 4][bc];
                mma_tf32(acc[0][nt], af[0], bf);
                mma_tf32(acc[1][nt], af[1], bf);
            }
        }
        __syncthreads();
    }

    // two-phase epilogue: stage 64 rows in smem, scatter that half's bucket
#pragma unroll
    for (int h2 = 0; h2 < 2; h2++) {
        if ((wm < 64) == (h2 == 0)) {
            int rbase = wm - h2 * 64;
#pragma unroll
            for (int mt = 0; mt < 2; mt++)
#pragma unroll
                for (int h = 0; h < 2; h++) {
                    int rl = rbase + mt * 16 + h * 8 + (lane >> 2);
#pragma unroll
                    for (int nt = 0; nt < 8; nt++) {
                        int col = wn + nt * 8 + 2 * (lane & 3);
                        *(float2*)&Ch[rl][col] =
                            make_float2(acc[mt][nt][h * 2 + 0], acc[mt][nt][h * 2 + 1]);
                    }
                }
        }
        __syncthreads();

        int bkt = bkt0 + h2;
        int lo = g_boff[bkt], hi = g_boff[bkt + 1];
        for (int i = lo + wid; i < hi; i += 8) {
            int sloc = g_bsrc[i] & 63;
            int dst  = g_bdst[i];
            float w  = g_bw[i];
            float4 v = *(const float4*)&Ch[sloc][lane * 4];
            v.x *= w; v.y *= w; v.z *= w; v.w *= w;
            float* p = g_acc + (size_t)dst * 128 + lane * 4;
            asm volatile("red.global.add.v4.f32 [%0], {%1,%2,%3,%4};"
                         :: "l"(p), "f"(v.x), "f"(v.y), "f"(v.z), "f"(v.w) : "memory");
        }
        __syncthreads();
    }
}

// ---------------- launch ----------------
extern "C" void kernel_launch(void* const* d_in, const int* in_sizes, int n_in,
                              void* d_out, int out_size) {
    const int*   edge_index   = (const int*)d_in[0];
    const int*   edge_type    = (const int*)d_in[1];
    const int*   node_indices = (const int*)d_in[2];
    const float* file_feats   = (const float*)d_in[3];
    const int*   file_idx     = (const int*)d_in[4];
    const float* domain_feats = (const float*)d_in[5];
    const int*   domain_idx   = (const int*)d_in[6];
    const float* ip_feats     = (const float*)d_in[7];
    const int*   ip_idx       = (const int*)d_in[8];
    const float* fallback     = (const float*)d_in[9];
    const float* Wf  = (const float*)d_in[10];
    const float* bf  = (const float*)d_in[11];
    const float* Wd  = (const float*)d_in[12];
    const float* bd  = (const float*)d_in[13];
    const float* Wi  = (const float*)d_in[14];
    const float* bi  = (const float*)d_in[15];
    const float* comp1  = (const float*)d_in[16];
    const float* bases1 = (const float*)d_in[17];
    const float* root1  = (const float*)d_in[18];
    const float* bias1  = (const float*)d_in[19];
    const float* comp2  = (const float*)d_in[20];
    const float* bases2 = (const float*)d_in[21];
    const float* root2  = (const float*)d_in[22];
    const float* bias2  = (const float*)d_in[23];
    const float* ln1_g  = (const float*)d_in[24];
    const float* ln1_b  = (const float*)d_in[25];
    const float* ln2_g  = (const float*)d_in[26];
    const float* ln2_b  = (const float*)d_in[27];
    const float* Wc1 = (const float*)d_in[28];
    const float* bc1 = (const float*)d_in[29];
    const float* Wc2 = (const float*)d_in[30];
    const float* bc2 = (const float*)d_in[31];
    float* out = (float*)d_out;

    float *px, *pacc, *phsel;
    cudaGetSymbolAddress((void**)&px,    g_x);
    cudaGetSymbolAddress((void**)&pacc,  g_acc);
    cudaGetSymbolAddress((void**)&phsel, g_hsel);

    // ---- build node features (tf32-rounded into g_x) ----
    k_copy_x<<<(Nn * Dd / 4 + 255) / 256, 256>>>(fallback);
    tgemm<<<157, 256>>>(file_feats,   nullptr, 20000, 256, Wf, px, bf, 0, 1, file_idx);
    tgemm<<<118, 256>>>(domain_feats, nullptr, 15000, 128, Wd, px, bd, 0, 1, domain_idx);
    tgemm<<<79,  256>>>(ip_feats,     nullptr, 10000, 64,  Wi, px, bi, 0, 1, ip_idx);

    // ---- edge counts + bucket sort by (relation, src/64) — reused by both layers ----
    k_zero_cnt<<<(Rr * Nn + 255) / 256, 256>>>();
    k_count<<<(Ee + 255) / 256, 256>>>(edge_index, edge_type);
    k_inv<<<(Rr * Nn + 255) / 256, 256>>>();
    k_scan<<<1, 1024>>>();
    k_place<<<(Ee + 255) / 256, 256>>>(edge_index, edge_type);

    dim3 fgrid(NTILE, Rr);

    // ---- layer 1 ----
    k_build_W<<<(Rr * Dd * Dd + 255) / 256, 256>>>(comp1, bases1);
    tgemm<<<NTILE, 256>>>(px, nullptr, Nn, 128, root1, pacc, bias1, 0, 0, nullptr);
    ftgemm<<<fgrid, 256>>>();
    k_ln<<<(Nn * 32 + 255) / 256, 256>>>(ln1_g, ln1_b, 1);

    // ---- layer 2 ----
    k_build_W<<<(Rr * Dd * Dd + 255) / 256, 256>>>(comp2, bases2);
    tgemm<<<NTILE, 256>>>(px, nullptr, Nn, 128, root2, pacc, bias2, 0, 0, nullptr);
    ftgemm<<<fgrid, 256>>>();
    k_ln<<<(Nn * 32 + 255) / 256, 256>>>(ln2_g, ln2_b, 0);

    // ---- classifier ----
    tgemm<<<(NSEL + 127) / 128, 256>>>(px, node_indices, NSEL, 128, Wc1,
                                       phsel, bc1, 1, 0, nullptr);
    k_final<<<(NSEL * NCc + 255) / 256, 256>>>(Wc2, bc2, out);
}

// round 6
// speedup vs baseline: 1.6570x; 1.0405x over previous
#include <cuda_runtime.h>
#include <cuda_bf16.h>

// Problem constants
#define Nn    50000
#define Dd    128
#define Rr    10
#define Ee    800000
#define NSEL  8192
#define NCc   12
#define NTILE 391                 // ceil(Nn/128)
#define NG    782                 // ceil(Nn/64) src groups
#define NBKT  (Rr * NG)           // 7820 buckets
#define SLOTS (Rr + 1)            // 10 relations + root

// dynamic smem for ftgemm: A(128x132 f32) + B double-buffer (2 x 32x136 f32)
#define SM_A_BYTES   (128 * 132 * 4)
#define SM_B_BYTES   (32 * 136 * 4)
#define SM_TOTAL     (SM_A_BYTES + 2 * SM_B_BYTES)   // 102400

// ---------------- device scratch (static allocations only) ----------------
__device__ float g_x[Nn * Dd];          // node features (tf32-rounded)
__device__ float g_acc[Nn * Dd];        // conv accumulator (fp32), kept zeroed between layers
__device__ float g_W[SLOTS * Dd * Dd];  // relation weights + root (tf32-rounded)
__device__ int   g_icnt[Rr * Nn];       // per-(r,dst) edge counts
__device__ float g_inv[Rr * Nn];        // 1/max(cnt,1)
__device__ float g_hsel[NSEL * Dd];     // classifier hidden
__device__ int   g_bcnt[NBKT];          // bucket counts
__device__ int   g_bcur[NBKT];          // bucket cursors
__device__ int   g_boff[NBKT + 1];      // bucket offsets
__device__ int   g_bsrc[Ee];            // bucketed edge src
__device__ int   g_bdst[Ee];            // bucketed edge dst
__device__ float g_bw[Ee];              // bucketed edge weight inv[r,dst]

// ---------------- helpers ----------------
__device__ __forceinline__ unsigned f2tf(float f) {
    unsigned u;
    asm("cvt.rna.tf32.f32 %0, %1;" : "=r"(u) : "f"(f));
    return u;
}
__device__ __forceinline__ float tf32r(float f) { return __uint_as_float(f2tf(f)); }

__device__ __forceinline__ void mma_tf32(float c[4], const unsigned a[4], const unsigned b[2]) {
    asm volatile("mma.sync.aligned.m16n8k8.row.col.f32.tf32.tf32.f32 "
                 "{%0,%1,%2,%3}, {%4,%5,%6,%7}, {%8,%9}, {%0,%1,%2,%3};"
                 : "+f"(c[0]), "+f"(c[1]), "+f"(c[2]), "+f"(c[3])
                 : "r"(a[0]), "r"(a[1]), "r"(a[2]), "r"(a[3]), "r"(b[0]), "r"(b[1]));
}

__device__ __forceinline__ void cp16(void* smem, const void* g, int srcsize) {
    unsigned a = (unsigned)__cvta_generic_to_shared(smem);
    asm volatile("cp.async.ca.shared.global [%0], [%1], 16, %2;"
                 :: "r"(a), "l"(g), "r"(srcsize));
}

// ---------------- small kernels ----------------
__global__ void k_copy_x(const float* __restrict__ src) {
    int i = blockIdx.x * blockDim.x + threadIdx.x;
    if (i >= Nn * Dd / 4) return;
    float4 v = ((const float4*)src)[i];
    v.x = tf32r(v.x); v.y = tf32r(v.y); v.z = tf32r(v.z); v.w = tf32r(v.w);
    ((float4*)g_x)[i] = v;
    ((float4*)g_acc)[i] = make_float4(0.f, 0.f, 0.f, 0.f);   // acc zeroed for layer 1
}

__global__ void k_build_W(const float* __restrict__ comp,
                          const float* __restrict__ bases,
                          const float* __restrict__ root) {
    int i = blockIdx.x * blockDim.x + threadIdx.x;
    if (i >= SLOTS * Dd * Dd) return;
    int slot = i >> 14;
    int idx  = i & 16383;
    float v;
    if (slot < Rr) {
        v = 0.f;
#pragma unroll
        for (int b = 0; b < 4; b++)
            v += comp[slot * 4 + b] * bases[b * Dd * Dd + idx];
    } else {
        v = root[idx];
    }
    g_W[i] = tf32r(v);
}

__global__ void k_zero_cnt() {
    int i = blockIdx.x * blockDim.x + threadIdx.x;
    if (i < Rr * Nn) g_icnt[i] = 0;
    if (i < NBKT) { g_bcnt[i] = 0; g_bcur[i] = 0; }
}

__global__ void k_count(const int* __restrict__ ei, const int* __restrict__ et) {
    int e = blockIdx.x * blockDim.x + threadIdx.x;
    if (e >= Ee) return;
    int r = et[e];
    atomicAdd(&g_icnt[r * Nn + ei[Ee + e]], 1);
    atomicAdd(&g_bcnt[r * NG + (ei[e] >> 6)], 1);
}

__global__ void k_inv() {
    int i = blockIdx.x * blockDim.x + threadIdx.x;
    if (i < Rr * Nn) g_inv[i] = 1.0f / fmaxf((float)g_icnt[i], 1.0f);
}

// single-block scan over NBKT bucket counts -> g_boff
__global__ void k_scan() {
    __shared__ int part[1024];
    int t = threadIdx.x;
    int s = 0;
#pragma unroll
    for (int j = 0; j < 8; j++) {
        int b = t * 8 + j;
        if (b < NBKT) s += g_bcnt[b];
    }
    part[t] = s;
    __syncthreads();
    for (int o = 1; o < 1024; o <<= 1) {
        int v = (t >= o) ? part[t - o] : 0;
        __syncthreads();
        part[t] += v;
        __syncthreads();
    }
    int run = (t > 0) ? part[t - 1] : 0;
#pragma unroll
    for (int j = 0; j < 8; j++) {
        int b = t * 8 + j;
        if (b < NBKT) { g_boff[b] = run; run += g_bcnt[b]; }
    }
    if (t == 0) g_boff[NBKT] = part[1023];
}

__global__ void k_place(const int* __restrict__ ei, const int* __restrict__ et) {
    int e = blockIdx.x * blockDim.x + threadIdx.x;
    if (e >= Ee) return;
    int r = et[e];
    int s = ei[e], t = ei[Ee + e];
    int key = r * NG + (s >> 6);
    int pos = g_boff[key] + atomicAdd(&g_bcur[key], 1);
    g_bsrc[pos] = s;
    g_bdst[pos] = t;
    g_bw[pos]   = g_inv[r * Nn + t];
}

// one warp per node: LayerNorm (+optional ReLU), g_acc -> g_x (tf32), then zero acc
__global__ void k_ln(const float* __restrict__ g, const float* __restrict__ b, int relu) {
    int gt = blockIdx.x * blockDim.x + threadIdx.x;
    int node = gt >> 5;
    if (node >= Nn) return;
    int lane = gt & 31;
    float4 v = ((const float4*)g_acc)[node * 32 + lane];
    float s = v.x + v.y + v.z + v.w;
    float q = v.x * v.x + v.y * v.y + v.z * v.z + v.w * v.w;
#pragma unroll
    for (int o = 16; o; o >>= 1) {
        s += __shfl_xor_sync(0xffffffffu, s, o);
        q += __shfl_xor_sync(0xffffffffu, q, o);
    }
    float mean = s * (1.f / 128.f);
    float var  = q * (1.f / 128.f) - mean * mean;
    float rstd = rsqrtf(var + 1e-5f);
    float4 gg = ((const float4*)g)[lane];
    float4 bb = ((const float4*)b)[lane];
    float4 o4;
    o4.x = (v.x - mean) * rstd * gg.x + bb.x;
    o4.y = (v.y - mean) * rstd * gg.y + bb.y;
    o4.z = (v.z - mean) * rstd * gg.z + bb.z;
    o4.w = (v.w - mean) * rstd * gg.w + bb.w;
    if (relu) {
        o4.x = fmaxf(o4.x, 0.f); o4.y = fmaxf(o4.y, 0.f);
        o4.z = fmaxf(o4.z, 0.f); o4.w = fmaxf(o4.w, 0.f);
    }
    o4.x = tf32r(o4.x); o4.y = tf32r(o4.y); o4.z = tf32r(o4.z); o4.w = tf32r(o4.w);
    ((float4*)g_x)[node * 32 + lane] = o4;
    ((float4*)g_acc)[node * 32 + lane] = make_float4(0.f, 0.f, 0.f, 0.f);  // ready for next layer
}

// final tiny GEMM
__global__ void k_final(const float* __restrict__ W, const float* __restrict__ b,
                        float* __restrict__ out) {
    int gt = blockIdx.x * blockDim.x + threadIdx.x;
    if (gt >= NSEL * NCc) return;
    int i = gt / NCc, c = gt % NCc;
    const float* hr = g_hsel + i * Dd;
    float s = b[c];
#pragma unroll 8
    for (int k = 0; k < Dd; k++) s += hr[k] * W[k * NCc + c];
    out[gt] = s;
}

// ---------------- dense tf32 GEMM (projections / classifier) --------
// C tile 128x128, 256 threads = 8 warps (4m x 2n), warp tile 32x64. N==128.
__global__ void __launch_bounds__(256)
tgemm(const float* __restrict__ A, const int* __restrict__ aIdx,
      int M, int K,
      const float* __restrict__ B,
      float* __restrict__ C,
      const float* __restrict__ bias, int relu, int tf32out,
      const int* __restrict__ rowIdx) {
    int row0 = blockIdx.x * 128;
    __shared__ unsigned As[128][36];
    __shared__ unsigned Bs[32][136];
    float acc[2][8][4];
#pragma unroll
    for (int mt = 0; mt < 2; mt++)
#pragma unroll
        for (int nt = 0; nt < 8; nt++)
#pragma unroll
            for (int q = 0; q < 4; q++) acc[mt][nt][q] = 0.f;

    int tid = threadIdx.x;
    int lane = tid & 31, wid = tid >> 5;
    int wm = (wid >> 1) * 32;
    int wn = (wid & 1) * 64;

    for (int kb = 0; kb < K; kb += 32) {
#pragma unroll
        for (int it = 0; it < 4; it++) {
            int idx = tid + it * 256;
            int m = idx >> 3;
            int kq = (idx & 7) * 4;
            float4 v = make_float4(0.f, 0.f, 0.f, 0.f);
            int row = row0 + m;
            if (row < M) {
                int ar = aIdx ? aIdx[row] : row;
                v = *(const float4*)&A[(size_t)ar * K + kb + kq];
            }
            As[m][kq + 0] = f2tf(v.x); As[m][kq + 1] = f2tf(v.y);
            As[m][kq + 2] = f2tf(v.z); As[m][kq + 3] = f2tf(v.w);
        }
#pragma unroll
        for (int it = 0; it < 4; it++) {
            int idx = tid + it * 256;
            int k = idx >> 5;
            int nq = (idx & 31) * 4;
            float4 v = *(const float4*)&B[(size_t)(kb + k) * 128 + nq];
            Bs[k][nq + 0] = f2tf(v.x); Bs[k][nq + 1] = f2tf(v.y);
            Bs[k][nq + 2] = f2tf(v.z); Bs[k][nq + 3] = f2tf(v.w);
        }
        __syncthreads();
#pragma unroll
        for (int ks = 0; ks < 4; ks++) {
            int k0 = ks * 8;
            unsigned af[2][4];
#pragma unroll
            for (int mt = 0; mt < 2; mt++) {
                int r = wm + mt * 16 + (lane >> 2);
                int c = k0 + (lane & 3);
                af[mt][0] = As[r][c];     af[mt][1] = As[r + 8][c];
                af[mt][2] = As[r][c + 4]; af[mt][3] = As[r + 8][c + 4];
            }
#pragma unroll
            for (int nt = 0; nt < 8; nt++) {
                unsigned bf[2];
                int br = k0 + (lane & 3);
                int bc = wn + nt * 8 + (lane >> 2);
                bf[0] = Bs[br][bc];
                bf[1] = Bs[br + 4][bc];
                mma_tf32(acc[0][nt], af[0], bf);
                mma_tf32(acc[1][nt], af[1], bf);
            }
        }
        __syncthreads();
    }

#pragma unroll
    for (int mt = 0; mt < 2; mt++) {
#pragma unroll
        for (int h = 0; h < 2; h++) {
            int row = row0 + wm + mt * 16 + (lane >> 2) + h * 8;
            if (row >= M) continue;
            int cr = rowIdx ? rowIdx[row] : row;
#pragma unroll
            for (int nt = 0; nt < 8; nt++) {
                int col = wn + nt * 8 + 2 * (lane & 3);
                float v0 = acc[mt][nt][h * 2 + 0];
                float v1 = acc[mt][nt][h * 2 + 1];
                if (bias) { v0 += bias[col]; v1 += bias[col + 1]; }
                if (relu) { v0 = fmaxf(v0, 0.f); v1 = fmaxf(v1, 0.f); }
                if (tf32out) { v0 = tf32r(v0); v1 = tf32r(v1); }
                *(float2*)&C[(size_t)cr * 128 + col] = make_float2(v0, v1);
            }
        }
    }
}

// ---------------- fused dense GEMM + edge scatter (pipelined) ----------------
// grid = (NTILE, SLOTS). Slot y<Rr: xw = x_tile @ W[y], staged to smem in 64-row
// halves, bucket (y, srcgroup) walked, w * xw[src] red.add into g_acc[dst].
// Slot y==Rr: root — xw + bias red.add directly into g_acc (acc pre-zeroed).
// A loaded once via cp.async; B (W chunks) double-buffered via cp.async.
__global__ void __launch_bounds__(256, 2)
ftgemm(const float* __restrict__ bias) {
    extern __shared__ __align__(16) char dsm[];
    float (*As)[132] = (float(*)[132])dsm;                            // 128x132
    float (*B0)[136] = (float(*)[136])(dsm + SM_A_BYTES);             // stage 0
    float (*B1)[136] = (float(*)[136])(dsm + SM_A_BYTES + SM_B_BYTES);// stage 1
    float (*Ch)[132] = (float(*)[132])(dsm + SM_A_BYTES);             // epilogue overlay

    int tile = blockIdx.x;
    int r    = blockIdx.y;
    int row0 = tile * 128;
    bool isRoot = (r == Rr);

    int bkt0 = 0;
    if (!isRoot) {
        bkt0 = r * NG + tile * 2;
        if (g_boff[bkt0] == g_boff[bkt0 + 2]) return;   // no edges for this (r, tile)
    }

    int tid = threadIdx.x;
    int lane = tid & 31, wid = tid >> 5;
    int wm = (wid >> 1) * 32;
    int wn = (wid & 1) * 64;

    const float* Wz = g_W + (size_t)r * (Dd * Dd);

    // ---- preamble: async-load whole A tile + B stages 0,1 ----
#pragma unroll
    for (int it = 0; it < 16; it++) {
        int idx = tid + it * 256;
        int m = idx >> 5;
        int q = (idx & 31) * 4;
        int row = row0 + m;
        cp16(&As[m][q], &g_x[(size_t)row * 128 + q], row < Nn ? 16 : 0);
    }
#pragma unroll
    for (int it = 0; it < 4; it++) {
        int idx = tid + it * 256;
        int k = idx >> 5;
        int nq = (idx & 31) * 4;
        cp16(&B0[k][nq], &Wz[(size_t)k * 128 + nq], 16);
    }
    asm volatile("cp.async.commit_group;");   // G0 = A + B(kb=0)
#pragma unroll
    for (int it = 0; it < 4; it++) {
        int idx = tid + it * 256;
        int k = idx >> 5;
        int nq = (idx & 31) * 4;
        cp16(&B1[k][nq], &Wz[(size_t)(32 + k) * 128 + nq], 16);
    }
    asm volatile("cp.async.commit_group;");   // G1 = B(kb=1)

    float acc[2][8][4];
#pragma unroll
    for (int mt = 0; mt < 2; mt++)
#pragma unroll
        for (int nt = 0; nt < 8; nt++)
#pragma unroll
            for (int q = 0; q < 4; q++) acc[mt][nt][q] = 0.f;

#pragma unroll
    for (int kb = 0; kb < 4; kb++) {
        if (kb < 3) asm volatile("cp.async.wait_group 1;" ::: "memory");
        else        asm volatile("cp.async.wait_group 0;" ::: "memory");
        __syncthreads();

        float (*Bs)[136] = (kb & 1) ? B1 : B0;
#pragma unroll
        for (int ks = 0; ks < 4; ks++) {
            int kg = kb * 32 + ks * 8;
            unsigned af[2][4];
#pragma unroll
            for (int mt = 0; mt < 2; mt++) {
                int rr = wm + mt * 16 + (lane >> 2);
                int cc = kg + (lane & 3);
                af[mt][0] = __float_as_uint(As[rr][cc]);
                af[mt][1] = __float_as_uint(As[rr + 8][cc]);
                af[mt][2] = __float_as_uint(As[rr][cc + 4]);
                af[mt][3] = __float_as_uint(As[rr + 8][cc + 4]);
            }
#pragma unroll
            for (int nt = 0; nt < 8; nt++) {
                unsigned bf[2];
                int br = ks * 8 + (lane & 3);
                int bc = wn + nt * 8 + (lane >> 2);
                bf[0] = __float_as_uint(Bs[br][bc]);
                bf[1] = __float_as_uint(Bs[br + 4][bc]);
                mma_tf32(acc[0][nt], af[0], bf);
                mma_tf32(acc[1][nt], af[1], bf);
            }
        }
        __syncthreads();

        if (kb < 2) {   // prefetch B(kb+2) into the stage just consumed
            float (*Bn)[136] = (kb & 1) ? B1 : B0;
#pragma unroll
            for (int it = 0; it < 4; it++) {
                int idx = tid + it * 256;
                int k = idx >> 5;
                int nq = (idx & 31) * 4;
                cp16(&Bn[k][nq], &Wz[(size_t)((kb + 2) * 32 + k) * 128 + nq], 16);
            }
            asm volatile("cp.async.commit_group;");
        }
    }

    // ---- epilogue ----
    if (isRoot) {
        // xw + bias red.add directly into g_acc (acc pre-zeroed; race-free adds)
#pragma unroll
        for (int mt = 0; mt < 2; mt++)
#pragma unroll
            for (int h = 0; h < 2; h++) {
                int row = row0 + wm + mt * 16 + (lane >> 2) + h * 8;
                if (row >= Nn) continue;
                float* outr = g_acc + (size_t)row * 128;
#pragma unroll
                for (int nt = 0; nt < 8; nt++) {
                    int col = wn + nt * 8 + 2 * (lane & 3);
                    float v0 = acc[mt][nt][h * 2 + 0] + bias[col];
                    float v1 = acc[mt][nt][h * 2 + 1] + bias[col + 1];
                    asm volatile("red.global.add.v2.f32 [%0], {%1,%2};"
                                 :: "l"(outr + col), "f"(v0), "f"(v1) : "memory");
                }
            }
        return;
    }

    // two-phase: stage 64 rows in smem, scatter that half's bucket
#pragma unroll
    for (int h2 = 0; h2 < 2; h2++) {
        if ((wm < 64) == (h2 == 0)) {
            int rbase = wm - h2 * 64;
#pragma unroll
            for (int mt = 0; mt < 2; mt++)
#pragma unroll
                for (int h = 0; h < 2; h++) {
                    int rl = rbase + mt * 16 + h * 8 + (lane >> 2);
#pragma unroll
                    for (int nt = 0; nt < 8; nt++) {
                        int col = wn + nt * 8 + 2 * (lane & 3);
                        *(float2*)&Ch[rl][col] =
                            make_float2(acc[mt][nt][h * 2 + 0], acc[mt][nt][h * 2 + 1]);
                    }
                }
        }
        __syncthreads();

        int bkt = bkt0 + h2;
        int lo = g_boff[bkt], hi = g_boff[bkt + 1];
        for (int i = lo + wid; i < hi; i += 8) {
            int sloc = g_bsrc[i] & 63;
            int dst  = g_bdst[i];
            float w  = g_bw[i];
            float4 v = *(const float4*)&Ch[sloc][lane * 4];
            v.x *= w; v.y *= w; v.z *= w; v.w *= w;
            float* p = g_acc + (size_t)dst * 128 + lane * 4;
            asm volatile("red.global.add.v4.f32 [%0], {%1,%2,%3,%4};"
                         :: "l"(p), "f"(v.x), "f"(v.y), "f"(v.z), "f"(v.w) : "memory");
        }
        __syncthreads();
    }
}

// ---------------- launch ----------------
extern "C" void kernel_launch(void* const* d_in, const int* in_sizes, int n_in,
                              void* d_out, int out_size) {
    const int*   edge_index   = (const int*)d_in[0];
    const int*   edge_type    = (const int*)d_in[1];
    const int*   node_indices = (const int*)d_in[2];
    const float* file_feats   = (const float*)d_in[3];
    const int*   file_idx     = (const int*)d_in[4];
    const float* domain_feats = (const float*)d_in[5];
    const int*   domain_idx   = (const int*)d_in[6];
    const float* ip_feats     = (const float*)d_in[7];
    const int*   ip_idx       = (const int*)d_in[8];
    const float* fallback     = (const float*)d_in[9];
    const float* Wf  = (const float*)d_in[10];
    const float* bf  = (const float*)d_in[11];
    const float* Wd  = (const float*)d_in[12];
    const float* bd  = (const float*)d_in[13];
    const float* Wi  = (const float*)d_in[14];
    const float* bi  = (const float*)d_in[15];
    const float* comp1  = (const float*)d_in[16];
    const float* bases1 = (const float*)d_in[17];
    const float* root1  = (const float*)d_in[18];
    const float* bias1  = (const float*)d_in[19];
    const float* comp2  = (const float*)d_in[20];
    const float* bases2 = (const float*)d_in[21];
    const float* root2  = (const float*)d_in[22];
    const float* bias2  = (const float*)d_in[23];
    const float* ln1_g  = (const float*)d_in[24];
    const float* ln1_b  = (const float*)d_in[25];
    const float* ln2_g  = (const float*)d_in[26];
    const float* ln2_b  = (const float*)d_in[27];
    const float* Wc1 = (const float*)d_in[28];
    const float* bc1 = (const float*)d_in[29];
    const float* Wc2 = (const float*)d_in[30];
    const float* bc2 = (const float*)d_in[31];
    float* out = (float*)d_out;

    float *px, *phsel;
    cudaGetSymbolAddress((void**)&px,    g_x);
    cudaGetSymbolAddress((void**)&phsel, g_hsel);

    static int smem_set = 0;
    if (!smem_set) {
        cudaFuncSetAttribute(ftgemm, cudaFuncAttributeMaxDynamicSharedMemorySize, SM_TOTAL);
        smem_set = 1;
    }

    // ---- build node features (tf32-rounded into g_x) + zero acc ----
    k_copy_x<<<(Nn * Dd / 4 + 255) / 256, 256>>>(fallback);
    tgemm<<<157, 256>>>(file_feats,   nullptr, 20000, 256, Wf, px, bf, 0, 1, file_idx);
    tgemm<<<118, 256>>>(domain_feats, nullptr, 15000, 128, Wd, px, bd, 0, 1, domain_idx);
    tgemm<<<79,  256>>>(ip_feats,     nullptr, 10000, 64,  Wi, px, bi, 0, 1, ip_idx);

    // ---- edge counts + bucket sort by (relation, src/64) — reused by both layers ----
    k_zero_cnt<<<(Rr * Nn + 255) / 256, 256>>>();
    k_count<<<(Ee + 255) / 256, 256>>>(edge_index, edge_type);
    k_inv<<<(Rr * Nn + 255) / 256, 256>>>();
    k_scan<<<1, 1024>>>();
    k_place<<<(Ee + 255) / 256, 256>>>(edge_index, edge_type);

    dim3 fgrid(NTILE, SLOTS);

    // ---- layer 1 ----
    k_build_W<<<(SLOTS * Dd * Dd + 255) / 256, 256>>>(comp1, bases1, root1);
    ftgemm<<<fgrid, 256, SM_TOTAL>>>(bias1);
    k_ln<<<(Nn * 32 + 255) / 256, 256>>>(ln1_g, ln1_b, 1);

    // ---- layer 2 ----
    k_build_W<<<(SLOTS * Dd * Dd + 255) / 256, 256>>>(comp2, bases2, root2);
    ftgemm<<<fgrid, 256, SM_TOTAL>>>(bias2);
    k_ln<<<(Nn * 32 + 255) / 256, 256>>>(ln2_g, ln2_b, 0);

    // ---- classifier ----
    tgemm<<<(NSEL + 127) / 128, 256>>>(px, node_indices, NSEL, 128, Wc1,
                                       phsel, bc1, 1, 0, nullptr);
    k_final<<<(NSEL * NCc + 255) / 256, 256>>>(Wc2, bc2, out);
}

// round 8
// speedup vs baseline: 1.9041x; 1.1491x over previous
#include <cuda_runtime.h>
#include <cuda_fp16.h>
#include <cstdint>

// Problem constants
#define Nn    50000
#define Dd    128
#define Rr    10
#define Ee    800000
#define NSEL  8192
#define NCc   12
#define NTILE 391                 // ceil(Nn/128)
#define NG    782                 // ceil(Nn/64) src groups
#define NBKT  (Rr * NG)
#define SLOTS (Rr + 1)            // 10 relations + root

// ftg_h smem: A half[128][136] + B half[128][136]; Ch f32[64][132] overlays B
#define SMH_A_BYTES (128 * 136 * 2)     // 34816
#define SMH_TOTAL   (2 * SMH_A_BYTES)   // 69632
#define CH_STRIDE   132

// ---------------- device scratch ----------------
__device__ float  g_x[Nn * Dd];           // f32 shadow of g_xh (exact float(half))
__device__ __half g_xh[Nn * Dd];          // node features, fp16
__device__ float  g_acc[Nn * Dd];         // conv accumulator (fp32), zeroed between layers
__device__ __half g_Wh[SLOTS * Dd * Dd];  // weights TRANSPOSED [slot][n][k], fp16
__device__ int    g_icnt[Rr * Nn];
__device__ float  g_inv[Rr * Nn];
__device__ float  g_hsel[NSEL * Dd];
__device__ int    g_bcnt[NBKT];
__device__ int    g_bcur[NBKT];
__device__ int    g_boff[NBKT + 1];
__device__ int    g_bsrc[Ee];
__device__ int    g_bdst[Ee];
__device__ float  g_bw[Ee];

// ---------------- helpers ----------------
__device__ __forceinline__ unsigned f2tf(float f) {
    unsigned u;
    asm("cvt.rna.tf32.f32 %0, %1;" : "=r"(u) : "f"(f));
    return u;
}
__device__ __forceinline__ float tf32r(float f) { return __uint_as_float(f2tf(f)); }

__device__ __forceinline__ void mma_tf32(float c[4], const unsigned a[4], const unsigned b[2]) {
    asm volatile("mma.sync.aligned.m16n8k8.row.col.f32.tf32.tf32.f32 "
                 "{%0,%1,%2,%3}, {%4,%5,%6,%7}, {%8,%9}, {%0,%1,%2,%3};"
                 : "+f"(c[0]), "+f"(c[1]), "+f"(c[2]), "+f"(c[3])
                 : "r"(a[0]), "r"(a[1]), "r"(a[2]), "r"(a[3]), "r"(b[0]), "r"(b[1]));
}

__device__ __forceinline__ void mma_f16(float c[4], unsigned a0, unsigned a1,
                                        unsigned a2, unsigned a3,
                                        unsigned b0, unsigned b1) {
    asm volatile("mma.sync.aligned.m16n8k16.row.col.f32.f16.f16.f32 "
                 "{%0,%1,%2,%3}, {%4,%5,%6,%7}, {%8,%9}, {%0,%1,%2,%3};"
                 : "+f"(c[0]), "+f"(c[1]), "+f"(c[2]), "+f"(c[3])
                 : "r"(a0), "r"(a1), "r"(a2), "r"(a3), "r"(b0), "r"(b1));
}

__device__ __forceinline__ void cp16(void* smem, const void* g, int srcsize) {
    unsigned a = (unsigned)__cvta_generic_to_shared(smem);
    asm volatile("cp.async.ca.shared.global [%0], [%1], 16, %2;"
                 :: "r"(a), "l"(g), "r"(srcsize));
}

// ---------------- small kernels ----------------
__global__ void k_copy_x(const float* __restrict__ src) {
    int i = blockIdx.x * blockDim.x + threadIdx.x;
    if (i >= Nn * Dd / 4) return;
    float4 v = ((const float4*)src)[i];
    __half h0 = __float2half_rn(v.x), h1 = __float2half_rn(v.y);
    __half h2 = __float2half_rn(v.z), h3 = __float2half_rn(v.w);
    __half2 p0 = __halves2half2(h0, h1), p1 = __halves2half2(h2, h3);
    ((uint2*)g_xh)[i] = make_uint2(*(unsigned*)&p0, *(unsigned*)&p1);
    ((float4*)g_x)[i] = make_float4(__half2float(h0), __half2float(h1),
                                    __half2float(h2), __half2float(h3));
    ((float4*)g_acc)[i] = make_float4(0.f, 0.f, 0.f, 0.f);
}

// builds W TRANSPOSED into fp16: g_Wh[slot][n][k]
__global__ void k_build_W(const float* __restrict__ comp,
                          const float* __restrict__ bases,
                          const float* __restrict__ root) {
    int i = blockIdx.x * blockDim.x + threadIdx.x;
    if (i >= SLOTS * Dd * Dd) return;
    int slot = i >> 14;
    int idx  = i & 16383;          // n*128 + k
    int n = idx >> 7, k = idx & 127;
    int src = k * 128 + n;         // [k][n] orientation in inputs
    float v;
    if (slot < Rr) {
        v = 0.f;
#pragma unroll
        for (int b = 0; b < 4; b++)
            v += comp[slot * 4 + b] * bases[b * Dd * Dd + src];
    } else {
        v = root[src];
    }
    g_Wh[i] = __float2half_rn(v);
}

__global__ void k_zero_cnt() {
    int i = blockIdx.x * blockDim.x + threadIdx.x;
    if (i < Rr * Nn) g_icnt[i] = 0;
    if (i < NBKT) { g_bcnt[i] = 0; g_bcur[i] = 0; }
}

__global__ void k_count(const int* __restrict__ ei, const int* __restrict__ et) {
    int e = blockIdx.x * blockDim.x + threadIdx.x;
    if (e >= Ee) return;
    int r = et[e];
    atomicAdd(&g_icnt[r * Nn + ei[Ee + e]], 1);
    atomicAdd(&g_bcnt[r * NG + (ei[e] >> 6)], 1);
}

__global__ void k_inv() {
    int i = blockIdx.x * blockDim.x + threadIdx.x;
    if (i < Rr * Nn) g_inv[i] = 1.0f / fmaxf((float)g_icnt[i], 1.0f);
}

__global__ void k_scan() {
    __shared__ int part[1024];
    int t = threadIdx.x;
    int s = 0;
#pragma unroll
    for (int j = 0; j < 8; j++) {
        int b = t * 8 + j;
        if (b < NBKT) s += g_bcnt[b];
    }
    part[t] = s;
    __syncthreads();
    for (int o = 1; o < 1024; o <<= 1) {
        int v = (t >= o) ? part[t - o] : 0;
        __syncthreads();
        part[t] += v;
        __syncthreads();
    }
    int run = (t > 0) ? part[t - 1] : 0;
#pragma unroll
    for (int j = 0; j < 8; j++) {
        int b = t * 8 + j;
        if (b < NBKT) { g_boff[b] = run; run += g_bcnt[b]; }
    }
    if (t == 0) g_boff[NBKT] = part[1023];
}

__global__ void k_place(const int* __restrict__ ei, const int* __restrict__ et) {
    int e = blockIdx.x * blockDim.x + threadIdx.x;
    if (e >= Ee) return;
    int r = et[e];
    int s = ei[e], t = ei[Ee + e];
    int key = r * NG + (s >> 6);
    int pos = g_boff[key] + atomicAdd(&g_bcur[key], 1);
    g_bsrc[pos] = s;
    g_bdst[pos] = t;
    g_bw[pos]   = g_inv[r * Nn + t];
}

// one warp per node: LayerNorm (+optional ReLU); writes g_xh (fp16) + g_x shadow; zeroes acc
__global__ void k_ln(const float* __restrict__ g, const float* __restrict__ b, int relu) {
    int gt = blockIdx.x * blockDim.x + threadIdx.x;
    int node = gt >> 5;
    if (node >= Nn) return;
    int lane = gt & 31;
    float4 v = ((const float4*)g_acc)[node * 32 + lane];
    float s = v.x + v.y + v.z + v.w;
    float q = v.x * v.x + v.y * v.y + v.z * v.z + v.w * v.w;
#pragma unroll
    for (int o = 16; o; o >>= 1) {
        s += __shfl_xor_sync(0xffffffffu, s, o);
        q += __shfl_xor_sync(0xffffffffu, q, o);
    }
    float mean = s * (1.f / 128.f);
    float var  = q * (1.f / 128.f) - mean * mean;
    float rstd = rsqrtf(var + 1e-5f);
    float4 gg = ((const float4*)g)[lane];
    float4 bb = ((const float4*)b)[lane];
    float4 o4;
    o4.x = (v.x - mean) * rstd * gg.x + bb.x;
    o4.y = (v.y - mean) * rstd * gg.y + bb.y;
    o4.z = (v.z - mean) * rstd * gg.z + bb.z;
    o4.w = (v.w - mean) * rstd * gg.w + bb.w;
    if (relu) {
        o4.x = fmaxf(o4.x, 0.f); o4.y = fmaxf(o4.y, 0.f);
        o4.z = fmaxf(o4.z, 0.f); o4.w = fmaxf(o4.w, 0.f);
    }
    __half h0 = __float2half_rn(o4.x), h1 = __float2half_rn(o4.y);
    __half h2 = __float2half_rn(o4.z), h3 = __float2half_rn(o4.w);
    __half2 p0 = __halves2half2(h0, h1), p1 = __halves2half2(h2, h3);
    ((uint2*)g_xh)[node * 32 + lane] = make_uint2(*(unsigned*)&p0, *(unsigned*)&p1);
    ((float4*)g_x)[node * 32 + lane] = make_float4(__half2float(h0), __half2float(h1),
                                                   __half2float(h2), __half2float(h3));
    ((float4*)g_acc)[node * 32 + lane] = make_float4(0.f, 0.f, 0.f, 0.f);
}

__global__ void k_final(const float* __restrict__ W, const float* __restrict__ b,
                        float* __restrict__ out) {
    int gt = blockIdx.x * blockDim.x + threadIdx.x;
    if (gt >= NSEL * NCc) return;
    int i = gt / NCc, c = gt % NCc;
    const float* hr = g_hsel + i * Dd;
    float s = b[c];
#pragma unroll 8
    for (int k = 0; k < Dd; k++) s += hr[k] * W[k * NCc + c];
    out[gt] = s;
}

// ---------------- dense tf32 mma.sync GEMM (projections / classifier) ----------
// When chalf != null: rounds output to fp16, stores g_xh-shadow pair (chalf + C f32).
__global__ void __launch_bounds__(256)
tgemm(const float* __restrict__ A, const int* __restrict__ aIdx,
      int M, int K,
      const float* __restrict__ B,
      float* __restrict__ C, __half* __restrict__ chalf,
      const float* __restrict__ bias, int relu,
      const int* __restrict__ rowIdx) {
    int row0 = blockIdx.x * 128;
    __shared__ unsigned As[128][36];
    __shared__ unsigned Bs[32][136];
    float acc[2][8][4];
#pragma unroll
    for (int mt = 0; mt < 2; mt++)
#pragma unroll
        for (int nt = 0; nt < 8; nt++)
#pragma unroll
            for (int q = 0; q < 4; q++) acc[mt][nt][q] = 0.f;

    int tid = threadIdx.x;
    int lane = tid & 31, wid = tid >> 5;
    int wm = (wid >> 1) * 32;
    int wn = (wid & 1) * 64;

    for (int kb = 0; kb < K; kb += 32) {
#pragma unroll
        for (int it = 0; it < 4; it++) {
            int idx = tid + it * 256;
            int m = idx >> 3;
            int kq = (idx & 7) * 4;
            float4 v = make_float4(0.f, 0.f, 0.f, 0.f);
            int row = row0 + m;
            if (row < M) {
                int ar = aIdx ? aIdx[row] : row;
                v = *(const float4*)&A[(size_t)ar * K + kb + kq];
            }
            As[m][kq + 0] = f2tf(v.x); As[m][kq + 1] = f2tf(v.y);
            As[m][kq + 2] = f2tf(v.z); As[m][kq + 3] = f2tf(v.w);
        }
#pragma unroll
        for (int it = 0; it < 4; it++) {
            int idx = tid + it * 256;
            int k = idx >> 5;
            int nq = (idx & 31) * 4;
            float4 v = *(const float4*)&B[(size_t)(kb + k) * 128 + nq];
            Bs[k][nq + 0] = f2tf(v.x); Bs[k][nq + 1] = f2tf(v.y);
            Bs[k][nq + 2] = f2tf(v.z); Bs[k][nq + 3] = f2tf(v.w);
        }
        __syncthreads();
#pragma unroll
        for (int ks = 0; ks < 4; ks++) {
            int k0 = ks * 8;
            unsigned af[2][4];
#pragma unroll
            for (int mt = 0; mt < 2; mt++) {
                int r = wm + mt * 16 + (lane >> 2);
                int c = k0 + (lane & 3);
                af[mt][0] = As[r][c];     af[mt][1] = As[r + 8][c];
                af[mt][2] = As[r][c + 4]; af[mt][3] = As[r + 8][c + 4];
            }
#pragma unroll
            for (int nt = 0; nt < 8; nt++) {
                unsigned bf[2];
                int br = k0 + (lane & 3);
                int bc = wn + nt * 8 + (lane >> 2);
                bf[0] = Bs[br][bc];
                bf[1] = Bs[br + 4][bc];
                mma_tf32(acc[0][nt], af[0], bf);
                mma_tf32(acc[1][nt], af[1], bf);
            }
        }
        __syncthreads();
    }

#pragma unroll
    for (int mt = 0; mt < 2; mt++) {
#pragma unroll
        for (int h = 0; h < 2; h++) {
            int row = row0 + wm + mt * 16 + (lane >> 2) + h * 8;
            if (row >= M) continue;
            int cr = rowIdx ? rowIdx[row] : row;
#pragma unroll
            for (int nt = 0; nt < 8; nt++) {
                int col = wn + nt * 8 + 2 * (lane & 3);
                float v0 = acc[mt][nt][h * 2 + 0];
                float v1 = acc[mt][nt][h * 2 + 1];
                if (bias) { v0 += bias[col]; v1 += bias[col + 1]; }
                if (relu) { v0 = fmaxf(v0, 0.f); v1 = fmaxf(v1, 0.f); }
                if (chalf) {
                    __half h0 = __float2half_rn(v0), h1 = __float2half_rn(v1);
                    __half2 p = __halves2half2(h0, h1);
                    *(unsigned*)&chalf[(size_t)cr * 128 + col] = *(unsigned*)&p;
                    v0 = __half2float(h0); v1 = __half2float(h1);
                }
                *(float2*)&C[(size_t)cr * 128 + col] = make_float2(v0, v1);
            }
        }
    }
}

// ---------------- fp16 fused dense GEMM + edge scatter ----------------
// grid = (NTILE, SLOTS). Slot y<Rr: xw = xh_tile @ Wh[y]^T via m16n8k16 HMMA,
// staged to smem Ch (overlaying B) in two 64-row halves, bucket (y,srcgroup)
// walked, w * xw[src] red.add into g_acc[dst]. Slot y==Rr: root + bias.
__global__ void __launch_bounds__(256, 2)
ftg_h(const float* __restrict__ bias) {
    extern __shared__ __align__(16) char dsm[];
    __half (*As)[136] = (__half(*)[136])dsm;
    __half (*Bs)[136] = (__half(*)[136])(dsm + SMH_A_BYTES);
    float  (*Ch)[CH_STRIDE] = (float(*)[CH_STRIDE])(dsm + SMH_A_BYTES);  // overlays Bs

    int tile = blockIdx.x;
    int r    = blockIdx.y;
    int row0 = tile * 128;
    bool isRoot = (r == Rr);

    int bkt0 = 0;
    if (!isRoot) {
        bkt0 = r * NG + tile * 2;
        if (g_boff[bkt0] == g_boff[bkt0 + 2]) return;
    }

    int tid = threadIdx.x;
    int lane = tid & 31, wid = tid >> 5;
    int wm = (wid >> 1) * 32;
    int wn = (wid & 1) * 64;

    const __half* Wz = g_Wh + (size_t)r * (Dd * Dd);

    // async-load A (128x128 half) and B (128x128 half): 16B chunks, 8 iters each
#pragma unroll
    for (int it = 0; it < 8; it++) {
        int idx = tid + it * 256;
        int m = idx >> 4, c8 = (idx & 15) * 8;
        int gr = row0 + m;
        cp16(&As[m][c8], &g_xh[(size_t)gr * 128 + c8], gr < Nn ? 16 : 0);
    }
#pragma unroll
    for (int it = 0; it < 8; it++) {
        int idx = tid + it * 256;
        int n = idx >> 4, c8 = (idx & 15) * 8;
        cp16(&Bs[n][c8], &Wz[(size_t)n * 128 + c8], 16);
    }
    asm volatile("cp.async.commit_group;");

    float acc[2][8][4];
#pragma unroll
    for (int mt = 0; mt < 2; mt++)
#pragma unroll
        for (int nt = 0; nt < 8; nt++)
#pragma unroll
            for (int q = 0; q < 4; q++) acc[mt][nt][q] = 0.f;

    asm volatile("cp.async.wait_group 0;" ::: "memory");
    __syncthreads();

    // 8 k16-steps over fully-resident tiles
#pragma unroll
    for (int ks = 0; ks < 8; ks++) {
        int kp = ks * 16 + (lane & 3) * 2;
        unsigned af[2][4];
#pragma unroll
        for (int mt = 0; mt < 2; mt++) {
            int rr = wm + mt * 16 + (lane >> 2);
            af[mt][0] = *(const unsigned*)&As[rr][kp];
            af[mt][1] = *(const unsigned*)&As[rr + 8][kp];
            af[mt][2] = *(const unsigned*)&As[rr][kp + 8];
            af[mt][3] = *(const unsigned*)&As[rr + 8][kp + 8];
        }
#pragma unroll
        for (int nt = 0; nt < 8; nt++) {
            int n = wn + nt * 8 + (lane >> 2);
            unsigned b0 = *(const unsigned*)&Bs[n][kp];
            unsigned b1 = *(const unsigned*)&Bs[n][kp + 8];
            mma_f16(acc[0][nt], af[0][0], af[0][1], af[0][2], af[0][3], b0, b1);
            mma_f16(acc[1][nt], af[1][0], af[1][1], af[1][2], af[1][3], b0, b1);
        }
    }
    __syncthreads();   // all warps done reading Bs before Ch overlay

    if (isRoot) {
        float4 bias4 = *(const float4*)&bias[(lane & 31) * 4];
        // bias4 layout mismatch with acc cols; add per-column instead (cols 2*(lane&3))
#pragma unroll
        for (int mt = 0; mt < 2; mt++)
#pragma unroll
            for (int h = 0; h < 2; h++) {
                int row = row0 + wm + mt * 16 + (lane >> 2) + h * 8;
                if (row >= Nn) continue;
                float* outr = g_acc + (size_t)row * 128;
#pragma unroll
                for (int nt = 0; nt < 8; nt++) {
                    int col = wn + nt * 8 + 2 * (lane & 3);
                    float v0 = acc[mt][nt][h * 2 + 0] + bias[col];
                    float v1 = acc[mt][nt][h * 2 + 1] + bias[col + 1];
                    asm volatile("red.global.add.v2.f32 [%0], {%1,%2};"
                                 :: "l"(outr + col), "f"(v0), "f"(v1) : "memory");
                }
            }
        (void)bias4;
        return;
    }

    // two-phase: stage 64 rows into Ch, scatter that half's bucket
#pragma unroll
    for (int h2 = 0; h2 < 2; h2++) {
        if ((wm < 64) == (h2 == 0)) {
            int rbase = wm - h2 * 64;
#pragma unroll
            for (int mt = 0; mt < 2; mt++)
#pragma unroll
                for (int h = 0; h < 2; h++) {
                    int rl = rbase + mt * 16 + h * 8 + (lane >> 2);
#pragma unroll
                    for (int nt = 0; nt < 8; nt++) {
                        int col = wn + nt * 8 + 2 * (lane & 3);
                        *(float2*)&Ch[rl][col] =
                            make_float2(acc[mt][nt][h * 2 + 0], acc[mt][nt][h * 2 + 1]);
                    }
                }
        }
        __syncthreads();

        int bkt = bkt0 + h2;
        int lo = g_boff[bkt], hi = g_boff[bkt + 1];
        for (int i = lo + wid; i < hi; i += 8) {
            int sloc = g_bsrc[i] & 63;
            int dst  = g_bdst[i];
            float w  = g_bw[i];
            float4 v = *(const float4*)&Ch[sloc][lane * 4];
            v.x *= w; v.y *= w; v.z *= w; v.w *= w;
            float* p = g_acc + (size_t)dst * 128 + lane * 4;
            asm volatile("red.global.add.v4.f32 [%0], {%1,%2,%3,%4};"
                         :: "l"(p), "f"(v.x), "f"(v.y), "f"(v.z), "f"(v.w) : "memory");
        }
        __syncthreads();
    }
}

// ---------------- launch ----------------
extern "C" void kernel_launch(void* const* d_in, const int* in_sizes, int n_in,
                              void* d_out, int out_size) {
    const int*   edge_index   = (const int*)d_in[0];
    const int*   edge_type    = (const int*)d_in[1];
    const int*   node_indices = (const int*)d_in[2];
    const float* file_feats   = (const float*)d_in[3];
    const int*   file_idx     = (const int*)d_in[4];
    const float* domain_feats = (const float*)d_in[5];
    const int*   domain_idx   = (const int*)d_in[6];
    const float* ip_feats     = (const float*)d_in[7];
    const int*   ip_idx       = (const int*)d_in[8];
    const float* fallback     = (const float*)d_in[9];
    const float* Wf  = (const float*)d_in[10];
    const float* bf  = (const float*)d_in[11];
    const float* Wd  = (const float*)d_in[12];
    const float* bd  = (const float*)d_in[13];
    const float* Wi  = (const float*)d_in[14];
    const float* bi  = (const float*)d_in[15];
    const float* comp1  = (const float*)d_in[16];
    const float* bases1 = (const float*)d_in[17];
    const float* root1  = (const float*)d_in[18];
    const float* bias1  = (const float*)d_in[19];
    const float* comp2  = (const float*)d_in[20];
    const float* bases2 = (const float*)d_in[21];
    const float* root2  = (const float*)d_in[22];
    const float* bias2  = (const float*)d_in[23];
    const float* ln1_g  = (const float*)d_in[24];
    const float* ln1_b  = (const float*)d_in[25];
    const float* ln2_g  = (const float*)d_in[26];
    const float* ln2_b  = (const float*)d_in[27];
    const float* Wc1 = (const float*)d_in[28];
    const float* bc1 = (const float*)d_in[29];
    const float* Wc2 = (const float*)d_in[30];
    const float* bc2 = (const float*)d_in[31];
    float* out = (float*)d_out;

    float  *px, *phsel;
    __half *pxh;
    cudaGetSymbolAddress((void**)&px,    g_x);
    cudaGetSymbolAddress((void**)&pxh,   g_xh);
    cudaGetSymbolAddress((void**)&phsel, g_hsel);

    static int smem_set = 0;
    if (!smem_set) {
        cudaFuncSetAttribute(ftg_h, cudaFuncAttributeMaxDynamicSharedMemorySize, SMH_TOTAL);
        smem_set = 1;
    }

    // ---- node features (fp16 into g_xh + f32 shadow) + zero acc ----
    k_copy_x<<<(Nn * Dd / 4 + 255) / 256, 256>>>(fallback);
    tgemm<<<157, 256>>>(file_feats,   nullptr, 20000, 256, Wf, px, pxh, bf, 0, file_idx);
    tgemm<<<118, 256>>>(domain_feats, nullptr, 15000, 128, Wd, px, pxh, bd, 0, domain_idx);
    tgemm<<<79,  256>>>(ip_feats,     nullptr, 10000, 64,  Wi, px, pxh, bi, 0, ip_idx);

    // ---- edge counts + bucket sort by (relation, src/64) ----
    k_zero_cnt<<<(Rr * Nn + 255) / 256, 256>>>();
    k_count<<<(Ee + 255) / 256, 256>>>(edge_index, edge_type);
    k_inv<<<(Rr * Nn + 255) / 256, 256>>>();
    k_scan<<<1, 1024>>>();
    k_place<<<(Ee + 255) / 256, 256>>>(edge_index, edge_type);

    dim3 fgrid(NTILE, SLOTS);

    // ---- layer 1 ----
    k_build_W<<<(SLOTS * Dd * Dd + 255) / 256, 256>>>(comp1, bases1, root1);
    ftg_h<<<fgrid, 256, SMH_TOTAL>>>(bias1);
    k_ln<<<(Nn * 32 + 255) / 256, 256>>>(ln1_g, ln1_b, 1);

    // ---- layer 2 ----
    k_build_W<<<(SLOTS * Dd * Dd + 255) / 256, 256>>>(comp2, bases2, root2);
    ftg_h<<<fgrid, 256, SMH_TOTAL>>>(bias2);
    k_ln<<<(Nn * 32 + 255) / 256, 256>>>(ln2_g, ln2_b, 0);

    // ---- classifier ----
    tgemm<<<(NSEL + 127) / 128, 256>>>(px, node_indices, NSEL, 128, Wc1,
                                       phsel, nullptr, bc1, 1, nullptr);
    k_final<<<(NSEL * NCc + 255) / 256, 256>>>(Wc2, bc2, out);
}

// round 9
// speedup vs baseline: 2.0826x; 1.0937x over previous
#include <cuda_runtime.h>
#include <cuda_fp16.h>
#include <cstdint>

// Problem constants
#define Nn    50000
#define Dd    128
#define Rr    10
#define Ee    800000
#define NSEL  8192
#define NCc   12
#define NTILE 391                 // ceil(Nn/128)
#define NG    782                 // ceil(Nn/64) src groups
#define NBKT  (Rr * NG)
#define SLOTS (Rr + 1)            // 10 relations + root

// ftg_h smem: A half[128][136] + B half[128][136]; Ch f32[64][132] overlays B
#define SMH_A_BYTES (128 * 136 * 2)     // 34816
#define SMH_TOTAL   (2 * SMH_A_BYTES)   // 69632
#define CH_STRIDE   132

// ---------------- device scratch ----------------
__device__ __half g_xh[Nn * Dd];          // node features, fp16
__device__ float  g_acc[Nn * Dd];         // conv accumulator (fp32), zeroed between layers
__device__ __half g_Wh[SLOTS * Dd * Dd];  // weights TRANSPOSED [slot][n][k], fp16
__device__ int    g_icnt[Rr * Nn];
__device__ float  g_inv[Rr * Nn];
__device__ float  g_hsel[NSEL * Dd];
__device__ int    g_bcnt[NBKT];
__device__ int    g_bcur[NBKT];
__device__ int    g_boff[NBKT + 1];
__device__ int    g_bsrc[Ee];
__device__ int    g_bdst[Ee];
__device__ float  g_bw[Ee];

// ---------------- helpers ----------------
__device__ __forceinline__ unsigned f2tf(float f) {
    unsigned u;
    asm("cvt.rna.tf32.f32 %0, %1;" : "=r"(u) : "f"(f));
    return u;
}

__device__ __forceinline__ void mma_tf32(float c[4], const unsigned a[4], const unsigned b[2]) {
    asm volatile("mma.sync.aligned.m16n8k8.row.col.f32.tf32.tf32.f32 "
                 "{%0,%1,%2,%3}, {%4,%5,%6,%7}, {%8,%9}, {%0,%1,%2,%3};"
                 : "+f"(c[0]), "+f"(c[1]), "+f"(c[2]), "+f"(c[3])
                 : "r"(a[0]), "r"(a[1]), "r"(a[2]), "r"(a[3]), "r"(b[0]), "r"(b[1]));
}

__device__ __forceinline__ void mma_f16(float c[4], unsigned a0, unsigned a1,
                                        unsigned a2, unsigned a3,
                                        unsigned b0, unsigned b1) {
    asm volatile("mma.sync.aligned.m16n8k16.row.col.f32.f16.f16.f32 "
                 "{%0,%1,%2,%3}, {%4,%5,%6,%7}, {%8,%9}, {%0,%1,%2,%3};"
                 : "+f"(c[0]), "+f"(c[1]), "+f"(c[2]), "+f"(c[3])
                 : "r"(a0), "r"(a1), "r"(a2), "r"(a3), "r"(b0), "r"(b1));
}

__device__ __forceinline__ void cp16(void* smem, const void* g, int srcsize) {
    unsigned a = (unsigned)__cvta_generic_to_shared(smem);
    asm volatile("cp.async.ca.shared.global [%0], [%1], 16, %2;"
                 :: "r"(a), "l"(g), "r"(srcsize));
}

// ---------------- small kernels ----------------
// copies fallback rows >= 45000 (rows < 45000 are overwritten by projections),
// zeroes acc for layer 1, zeroes all counters (absorbs k_zero_cnt).
__global__ void k_copy_x(const float* __restrict__ src) {
    int i = blockIdx.x * blockDim.x + threadIdx.x;
    if (i >= Nn * Dd / 4) return;
    if (i >= 45000 * 32) {
        float4 v = ((const float4*)src)[i];
        __half2 p0 = __halves2half2(__float2half_rn(v.x), __float2half_rn(v.y));
        __half2 p1 = __halves2half2(__float2half_rn(v.z), __float2half_rn(v.w));
        ((uint2*)g_xh)[i] = make_uint2(*(unsigned*)&p0, *(unsigned*)&p1);
    }
    ((float4*)g_acc)[i] = make_float4(0.f, 0.f, 0.f, 0.f);
    if (i < Rr * Nn) g_icnt[i] = 0;
    if (i < NBKT) { g_bcnt[i] = 0; g_bcur[i] = 0; }
}

// builds W TRANSPOSED into fp16: g_Wh[slot][n][k]
__global__ void k_build_W(const float* __restrict__ comp,
                          const float* __restrict__ bases,
                          const float* __restrict__ root) {
    int i = blockIdx.x * blockDim.x + threadIdx.x;
    if (i >= SLOTS * Dd * Dd) return;
    int slot = i >> 14;
    int idx  = i & 16383;          // n*128 + k
    int n = idx >> 7, k = idx & 127;
    int src = k * 128 + n;         // [k][n] orientation in inputs
    float v;
    if (slot < Rr) {
        v = 0.f;
#pragma unroll
        for (int b = 0; b < 4; b++)
            v += comp[slot * 4 + b] * bases[b * Dd * Dd + src];
    } else {
        v = root[src];
    }
    g_Wh[i] = __float2half_rn(v);
}

__global__ void k_count(const int* __restrict__ ei, const int* __restrict__ et) {
    int e = blockIdx.x * blockDim.x + threadIdx.x;
    if (e >= Ee) return;
    int r = et[e];
    atomicAdd(&g_icnt[r * Nn + ei[Ee + e]], 1);
    atomicAdd(&g_bcnt[r * NG + (ei[e] >> 6)], 1);
}

__global__ void k_inv() {
    int i = blockIdx.x * blockDim.x + threadIdx.x;
    if (i < Rr * Nn) g_inv[i] = 1.0f / fmaxf((float)g_icnt[i], 1.0f);
}

__global__ void k_scan() {
    __shared__ int part[1024];
    int t = threadIdx.x;
    int s = 0;
#pragma unroll
    for (int j = 0; j < 8; j++) {
        int b = t * 8 + j;
        if (b < NBKT) s += g_bcnt[b];
    }
    part[t] = s;
    __syncthreads();
    for (int o = 1; o < 1024; o <<= 1) {
        int v = (t >= o) ? part[t - o] : 0;
        __syncthreads();
        part[t] += v;
        __syncthreads();
    }
    int run = (t > 0) ? part[t - 1] : 0;
#pragma unroll
    for (int j = 0; j < 8; j++) {
        int b = t * 8 + j;
        if (b < NBKT) { g_boff[b] = run; run += g_bcnt[b]; }
    }
    if (t == 0) g_boff[NBKT] = part[1023];
}

__global__ void k_place(const int* __restrict__ ei, const int* __restrict__ et) {
    int e = blockIdx.x * blockDim.x + threadIdx.x;
    if (e >= Ee) return;
    int r = et[e];
    int s = ei[e], t = ei[Ee + e];
    int key = r * NG + (s >> 6);
    int pos = g_boff[key] + atomicAdd(&g_bcur[key], 1);
    g_bsrc[pos] = s;
    g_bdst[pos] = t;
    g_bw[pos]   = g_inv[r * Nn + t];
}

// one warp per node: LayerNorm (+optional ReLU) -> g_xh (fp16); zeroes acc
__global__ void k_ln(const float* __restrict__ g, const float* __restrict__ b, int relu) {
    int gt = blockIdx.x * blockDim.x + threadIdx.x;
    int node = gt >> 5;
    if (node >= Nn) return;
    int lane = gt & 31;
    float4 v = ((const float4*)g_acc)[node * 32 + lane];
    float s = v.x + v.y + v.z + v.w;
    float q = v.x * v.x + v.y * v.y + v.z * v.z + v.w * v.w;
#pragma unroll
    for (int o = 16; o; o >>= 1) {
        s += __shfl_xor_sync(0xffffffffu, s, o);
        q += __shfl_xor_sync(0xffffffffu, q, o);
    }
    float mean = s * (1.f / 128.f);
    float var  = q * (1.f / 128.f) - mean * mean;
    float rstd = rsqrtf(var + 1e-5f);
    float4 gg = ((const float4*)g)[lane];
    float4 bb = ((const float4*)b)[lane];
    float4 o4;
    o4.x = (v.x - mean) * rstd * gg.x + bb.x;
    o4.y = (v.y - mean) * rstd * gg.y + bb.y;
    o4.z = (v.z - mean) * rstd * gg.z + bb.z;
    o4.w = (v.w - mean) * rstd * gg.w + bb.w;
    if (relu) {
        o4.x = fmaxf(o4.x, 0.f); o4.y = fmaxf(o4.y, 0.f);
        o4.z = fmaxf(o4.z, 0.f); o4.w = fmaxf(o4.w, 0.f);
    }
    __half2 p0 = __halves2half2(__float2half_rn(o4.x), __float2half_rn(o4.y));
    __half2 p1 = __halves2half2(__float2half_rn(o4.z), __float2half_rn(o4.w));
    ((uint2*)g_xh)[node * 32 + lane] = make_uint2(*(unsigned*)&p0, *(unsigned*)&p1);
    ((float4*)g_acc)[node * 32 + lane] = make_float4(0.f, 0.f, 0.f, 0.f);
}

__global__ void k_final(const float* __restrict__ W, const float* __restrict__ b,
                        float* __restrict__ out) {
    int gt = blockIdx.x * blockDim.x + threadIdx.x;
    if (gt >= NSEL * NCc) return;
    int i = gt / NCc, c = gt % NCc;
    const float* hr = g_hsel + i * Dd;
    float s = b[c];
#pragma unroll 8
    for (int k = 0; k < Dd; k++) s += hr[k] * W[k * NCc + c];
    out[gt] = s;
}

// ---------------- fused projection GEMM (3 segments, one launch) ----------------
// tf32 math (identical to before). Writes fp16 into g_xh at rowIdx-scattered rows.
__global__ void __launch_bounds__(256)
proj(const float* A0, const float* W0, const float* b0, const int* x0, int M0, int K0,
     const float* A1, const float* W1, const float* b1, const int* x1, int M1, int K1,
     const float* A2, const float* W2, const float* b2, const int* x2, int M2, int K2,
     int nb0, int nb1) {
    int b = blockIdx.x;
    const float *A, *B, *bias;
    const int* rowIdx;
    int M, K, row0;
    if (b < nb0)            { A = A0; B = W0; bias = b0; rowIdx = x0; M = M0; K = K0; row0 = b * 128; }
    else if (b < nb0 + nb1) { A = A1; B = W1; bias = b1; rowIdx = x1; M = M1; K = K1; row0 = (b - nb0) * 128; }
    else                    { A = A2; B = W2; bias = b2; rowIdx = x2; M = M2; K = K2; row0 = (b - nb0 - nb1) * 128; }

    __shared__ unsigned As[128][36];
    __shared__ unsigned Bs[32][136];
    float acc[2][8][4];
#pragma unroll
    for (int mt = 0; mt < 2; mt++)
#pragma unroll
        for (int nt = 0; nt < 8; nt++)
#pragma unroll
            for (int q = 0; q < 4; q++) acc[mt][nt][q] = 0.f;

    int tid = threadIdx.x;
    int lane = tid & 31, wid = tid >> 5;
    int wm = (wid >> 1) * 32;
    int wn = (wid & 1) * 64;

    for (int kb = 0; kb < K; kb += 32) {
#pragma unroll
        for (int it = 0; it < 4; it++) {
            int idx = tid + it * 256;
            int m = idx >> 3;
            int kq = (idx & 7) * 4;
            float4 v = make_float4(0.f, 0.f, 0.f, 0.f);
            int row = row0 + m;
            if (row < M) v = *(const float4*)&A[(size_t)row * K + kb + kq];
            As[m][kq + 0] = f2tf(v.x); As[m][kq + 1] = f2tf(v.y);
            As[m][kq + 2] = f2tf(v.z); As[m][kq + 3] = f2tf(v.w);
        }
#pragma unroll
        for (int it = 0; it < 4; it++) {
            int idx = tid + it * 256;
            int k = idx >> 5;
            int nq = (idx & 31) * 4;
            float4 v = *(const float4*)&B[(size_t)(kb + k) * 128 + nq];
            Bs[k][nq + 0] = f2tf(v.x); Bs[k][nq + 1] = f2tf(v.y);
            Bs[k][nq + 2] = f2tf(v.z); Bs[k][nq + 3] = f2tf(v.w);
        }
        __syncthreads();
#pragma unroll
        for (int ks = 0; ks < 4; ks++) {
            int k0 = ks * 8;
            unsigned af[2][4];
#pragma unroll
            for (int mt = 0; mt < 2; mt++) {
                int r = wm + mt * 16 + (lane >> 2);
                int c = k0 + (lane & 3);
                af[mt][0] = As[r][c];     af[mt][1] = As[r + 8][c];
                af[mt][2] = As[r][c + 4]; af[mt][3] = As[r + 8][c + 4];
            }
#pragma unroll
            for (int nt = 0; nt < 8; nt++) {
                unsigned bf[2];
                int br = k0 + (lane & 3);
                int bc = wn + nt * 8 + (lane >> 2);
                bf[0] = Bs[br][bc];
                bf[1] = Bs[br + 4][bc];
                mma_tf32(acc[0][nt], af[0], bf);
                mma_tf32(acc[1][nt], af[1], bf);
            }
        }
        __syncthreads();
    }

#pragma unroll
    for (int mt = 0; mt < 2; mt++) {
#pragma unroll
        for (int h = 0; h < 2; h++) {
            int row = row0 + wm + mt * 16 + (lane >> 2) + h * 8;
            if (row >= M) continue;
            int cr = rowIdx[row];
#pragma unroll
            for (int nt = 0; nt < 8; nt++) {
                int col = wn + nt * 8 + 2 * (lane & 3);
                float v0 = acc[mt][nt][h * 2 + 0] + bias[col];
                float v1 = acc[mt][nt][h * 2 + 1] + bias[col + 1];
                __half2 p = __halves2half2(__float2half_rn(v0), __float2half_rn(v1));
                *(unsigned*)&g_xh[(size_t)cr * 128 + col] = *(unsigned*)&p;
            }
        }
    }
}

// ---------------- classifier GEMM: half input (exact cvt), tf32 math, f32 out ----
__global__ void __launch_bounds__(256)
cgemm(const int* __restrict__ aIdx, const float* __restrict__ B,
      const float* __restrict__ bias) {
    int row0 = blockIdx.x * 128;
    __shared__ unsigned As[128][36];
    __shared__ unsigned Bs[32][136];
    float acc[2][8][4];
#pragma unroll
    for (int mt = 0; mt < 2; mt++)
#pragma unroll
        for (int nt = 0; nt < 8; nt++)
#pragma unroll
            for (int q = 0; q < 4; q++) acc[mt][nt][q] = 0.f;

    int tid = threadIdx.x;
    int lane = tid & 31, wid = tid >> 5;
    int wm = (wid >> 1) * 32;
    int wn = (wid & 1) * 64;

    for (int kb = 0; kb < 128; kb += 32) {
#pragma unroll
        for (int it = 0; it < 4; it++) {
            int idx = tid + it * 256;
            int m = idx >> 3;
            int kq = (idx & 7) * 4;
            int row = row0 + m;
            int ar = aIdx[row];   // NSEL multiple of 128, no guard needed
            const __half* src = &g_xh[(size_t)ar * 128 + kb + kq];
            // half -> f32 -> tf32 is exact
            As[m][kq + 0] = f2tf(__half2float(src[0]));
            As[m][kq + 1] = f2tf(__half2float(src[1]));
            As[m][kq + 2] = f2tf(__half2float(src[2]));
            As[m][kq + 3] = f2tf(__half2float(src[3]));
        }
#pragma unroll
        for (int it = 0; it < 4; it++) {
            int idx = tid + it * 256;
            int k = idx >> 5;
            int nq = (idx & 31) * 4;
            float4 v = *(const float4*)&B[(size_t)(kb + k) * 128 + nq];
            Bs[k][nq + 0] = f2tf(v.x); Bs[k][nq + 1] = f2tf(v.y);
            Bs[k][nq + 2] = f2tf(v.z); Bs[k][nq + 3] = f2tf(v.w);
        }
        __syncthreads();
#pragma unroll
        for (int ks = 0; ks < 4; ks++) {
            int k0 = ks * 8;
            unsigned af[2][4];
#pragma unroll
            for (int mt = 0; mt < 2; mt++) {
                int r = wm + mt * 16 + (lane >> 2);
                int c = k0 + (lane & 3);
                af[mt][0] = As[r][c];     af[mt][1] = As[r + 8][c];
                af[mt][2] = As[r][c + 4]; af[mt][3] = As[r + 8][c + 4];
            }
#pragma unroll
            for (int nt = 0; nt < 8; nt++) {
                unsigned bf[2];
                int br = k0 + (lane & 3);
                int bc = wn + nt * 8 + (lane >> 2);
                bf[0] = Bs[br][bc];
                bf[1] = Bs[br + 4][bc];
                mma_tf32(acc[0][nt], af[0], bf);
                mma_tf32(acc[1][nt], af[1], bf);
            }
        }
        __syncthreads();
    }

#pragma unroll
    for (int mt = 0; mt < 2; mt++) {
#pragma unroll
        for (int h = 0; h < 2; h++) {
            int row = row0 + wm + mt * 16 + (lane >> 2) + h * 8;
#pragma unroll
            for (int nt = 0; nt < 8; nt++) {
                int col = wn + nt * 8 + 2 * (lane & 3);
                float v0 = fmaxf(acc[mt][nt][h * 2 + 0] + bias[col], 0.f);
                float v1 = fmaxf(acc[mt][nt][h * 2 + 1] + bias[col + 1], 0.f);
                *(float2*)&g_hsel[(size_t)row * 128 + col] = make_float2(v0, v1);
            }
        }
    }
}

// ---------------- fp16 fused dense GEMM + edge scatter ----------------
__global__ void __launch_bounds__(256, 2)
ftg_h(const float* __restrict__ bias) {
    extern __shared__ __align__(16) char dsm[];
    __half (*As)[136] = (__half(*)[136])dsm;
    __half (*Bs)[136] = (__half(*)[136])(dsm + SMH_A_BYTES);
    float  (*Ch)[CH_STRIDE] = (float(*)[CH_STRIDE])(dsm + SMH_A_BYTES);  // overlays Bs

    int tile = blockIdx.x;
    int r    = blockIdx.y;
    int row0 = tile * 128;
    bool isRoot = (r == Rr);

    int bkt0 = 0;
    if (!isRoot) {
        bkt0 = r * NG + tile * 2;
        if (g_boff[bkt0] == g_boff[bkt0 + 2]) return;
    }

    int tid = threadIdx.x;
    int lane = tid & 31, wid = tid >> 5;
    int wm = (wid >> 1) * 32;
    int wn = (wid & 1) * 64;

    const __half* Wz = g_Wh + (size_t)r * (Dd * Dd);

#pragma unroll
    for (int it = 0; it < 8; it++) {
        int idx = tid + it * 256;
        int m = idx >> 4, c8 = (idx & 15) * 8;
        int gr = row0 + m;
        cp16(&As[m][c8], &g_xh[(size_t)gr * 128 + c8], gr < Nn ? 16 : 0);
    }
#pragma unroll
    for (int it = 0; it < 8; it++) {
        int idx = tid + it * 256;
        int n = idx >> 4, c8 = (idx & 15) * 8;
        cp16(&Bs[n][c8], &Wz[(size_t)n * 128 + c8], 16);
    }
    asm volatile("cp.async.commit_group;");

    float acc[2][8][4];
#pragma unroll
    for (int mt = 0; mt < 2; mt++)
#pragma unroll
        for (int nt = 0; nt < 8; nt++)
#pragma unroll
            for (int q = 0; q < 4; q++) acc[mt][nt][q] = 0.f;

    asm volatile("cp.async.wait_group 0;" ::: "memory");
    __syncthreads();

#pragma unroll
    for (int ks = 0; ks < 8; ks++) {
        int kp = ks * 16 + (lane & 3) * 2;
        unsigned af[2][4];
#pragma unroll
        for (int mt = 0; mt < 2; mt++) {
            int rr = wm + mt * 16 + (lane >> 2);
            af[mt][0] = *(const unsigned*)&As[rr][kp];
            af[mt][1] = *(const unsigned*)&As[rr + 8][kp];
            af[mt][2] = *(const unsigned*)&As[rr][kp + 8];
            af[mt][3] = *(const unsigned*)&As[rr + 8][kp + 8];
        }
#pragma unroll
        for (int nt = 0; nt < 8; nt++) {
            int n = wn + nt * 8 + (lane >> 2);
            unsigned b0 = *(const unsigned*)&Bs[n][kp];
            unsigned b1 = *(const unsigned*)&Bs[n][kp + 8];
            mma_f16(acc[0][nt], af[0][0], af[0][1], af[0][2], af[0][3], b0, b1);
            mma_f16(acc[1][nt], af[1][0], af[1][1], af[1][2], af[1][3], b0, b1);
        }
    }
    __syncthreads();   // all warps done reading Bs before Ch overlay

    if (isRoot) {
#pragma unroll
        for (int mt = 0; mt < 2; mt++)
#pragma unroll
            for (int h = 0; h < 2; h++) {
                int row = row0 + wm + mt * 16 + (lane >> 2) + h * 8;
                if (row >= Nn) continue;
                float* outr = g_acc + (size_t)row * 128;
#pragma unroll
                for (int nt = 0; nt < 8; nt++) {
                    int col = wn + nt * 8 + 2 * (lane & 3);
                    float v0 = acc[mt][nt][h * 2 + 0] + bias[col];
                    float v1 = acc[mt][nt][h * 2 + 1] + bias[col + 1];
                    asm volatile("red.global.add.v2.f32 [%0], {%1,%2};"
                                 :: "l"(outr + col), "f"(v0), "f"(v1) : "memory");
                }
            }
        return;
    }

    // two-phase: stage 64 rows into Ch, scatter that half's bucket (pipelined)
#pragma unroll
    for (int h2 = 0; h2 < 2; h2++) {
        if ((wm < 64) == (h2 == 0)) {
            int rbase = wm - h2 * 64;
#pragma unroll
            for (int mt = 0; mt < 2; mt++)
#pragma unroll
                for (int h = 0; h < 2; h++) {
                    int rl = rbase + mt * 16 + h * 8 + (lane >> 2);
#pragma unroll
                    for (int nt = 0; nt < 8; nt++) {
                        int col = wn + nt * 8 + 2 * (lane & 3);
                        *(float2*)&Ch[rl][col] =
                            make_float2(acc[mt][nt][h * 2 + 0], acc[mt][nt][h * 2 + 1]);
                    }
                }
        }
        __syncthreads();

        int bkt = bkt0 + h2;
        int lo = g_boff[bkt], hi = g_boff[bkt + 1];
        int i = lo + wid;
        int nsrc = 0, ndst = 0;
        float nw = 0.f;
        if (i < hi) { nsrc = g_bsrc[i]; ndst = g_bdst[i]; nw = g_bw[i]; }
        while (i < hi) {
            int sloc = nsrc & 63;
            int dst  = ndst;
            float w  = nw;
            int inext = i + 8;
            if (inext < hi) { nsrc = g_bsrc[inext]; ndst = g_bdst[inext]; nw = g_bw[inext]; }
            float4 v = *(const float4*)&Ch[sloc][lane * 4];
            v.x *= w; v.y *= w; v.z *= w; v.w *= w;
            float* p = g_acc + (size_t)dst * 128 + lane * 4;
            asm volatile("red.global.add.v4.f32 [%0], {%1,%2,%3,%4};"
                         :: "l"(p), "f"(v.x), "f"(v.y), "f"(v.z), "f"(v.w) : "memory");
            i = inext;
        }
        __syncthreads();
    }
}

// ---------------- launch ----------------
extern "C" void kernel_launch(void* const* d_in, const int* in_sizes, int n_in,
                              void* d_out, int out_size) {
    const int*   edge_index   = (const int*)d_in[0];
    const int*   edge_type    = (const int*)d_in[1];
    const int*   node_indices = (const int*)d_in[2];
    const float* file_feats   = (const float*)d_in[3];
    const int*   file_idx     = (const int*)d_in[4];
    const float* domain_feats = (const float*)d_in[5];
    const int*   domain_idx   = (const int*)d_in[6];
    const float* ip_feats     = (const float*)d_in[7];
    const int*   ip_idx       = (const int*)d_in[8];
    const float* fallback     = (const float*)d_in[9];
    const float* Wf  = (const float*)d_in[10];
    const float* bf  = (const float*)d_in[11];
    const float* Wd  = (const float*)d_in[12];
    const float* bd  = (const float*)d_in[13];
    const float* Wi  = (const float*)d_in[14];
    const float* bi  = (const float*)d_in[15];
    const float* comp1  = (const float*)d_in[16];
    const float* bases1 = (const float*)d_in[17];
    const float* root1  = (const float*)d_in[18];
    const float* bias1  = (const float*)d_in[19];
    const float* comp2  = (const float*)d_in[20];
    const float* bases2 = (const float*)d_in[21];
    const float* root2  = (const float*)d_in[22];
    const float* bias2  = (const float*)d_in[23];
    const float* ln1_g  = (const float*)d_in[24];
    const float* ln1_b  = (const float*)d_in[25];
    const float* ln2_g  = (const float*)d_in[26];
    const float* ln2_b  = (const float*)d_in[27];
    const float* Wc1 = (const float*)d_in[28];
    const float* bc1 = (const float*)d_in[29];
    const float* Wc2 = (const float*)d_in[30];
    const float* bc2 = (const float*)d_in[31];
    float* out = (float*)d_out;

    static int smem_set = 0;
    if (!smem_set) {
        cudaFuncSetAttribute(ftg_h, cudaFuncAttributeMaxDynamicSharedMemorySize, SMH_TOTAL);
        smem_set = 1;
    }

    // ---- node features + zero acc/counters ----
    k_copy_x<<<(Nn * Dd / 4 + 255) / 256, 256>>>(fallback);
    int nb0 = 157, nb1 = 118, nb2 = 79;   // ceil(20000/128), ceil(15000/128), ceil(10000/128)
    proj<<<nb0 + nb1 + nb2, 256>>>(file_feats,   Wf, bf, file_idx,   20000, 256,
                                   domain_feats, Wd, bd, domain_idx, 15000, 128,
                                   ip_feats,     Wi, bi, ip_idx,     10000, 64,
                                   nb0, nb1);

    // ---- edge counts + bucket sort by (relation, src/64) ----
    k_count<<<(Ee + 255) / 256, 256>>>(edge_index, edge_type);
    k_inv<<<(Rr * Nn + 255) / 256, 256>>>();
    k_scan<<<1, 1024>>>();
    k_place<<<(Ee + 255) / 256, 256>>>(edge_index, edge_type);

    dim3 fgrid(NTILE, SLOTS);

    // ---- layer 1 ----
    k_build_W<<<(SLOTS * Dd * Dd + 255) / 256, 256>>>(comp1, bases1, root1);
    ftg_h<<<fgrid, 256, SMH_TOTAL>>>(bias1);
    k_ln<<<(Nn * 32 + 255) / 256, 256>>>(ln1_g, ln1_b, 1);

    // ---- layer 2 ----
    k_build_W<<<(SLOTS * Dd * Dd + 255) / 256, 256>>>(comp2, bases2, root2);
    ftg_h<<<fgrid, 256, SMH_TOTAL>>>(bias2);
    k_ln<<<(Nn * 32 + 255) / 256, 256>>>(ln2_g, ln2_b, 0);

    // ---- classifier ----
    cgemm<<<NSEL / 128, 256>>>(node_indices, Wc1, bc1);
    k_final<<<(NSEL * NCc + 255) / 256, 256>>>(Wc2, bc2, out);
}

// round 10
// speedup vs baseline: 2.1462x; 1.0306x over previous
#include <cuda_runtime.h>
#include <cuda_fp16.h>
#include <cstdint>

// Problem constants
#define Nn    50000
#define Dd    128
#define Rr    10
#define Ee    800000
#define NSEL  8192
#define NCc   12
#define NTILE 391                 // ceil(Nn/128)
#define NG    782                 // ceil(Nn/64) src groups
#define NBKT  (Rr * NG)
#define SLOTS (Rr + 1)            // 10 relations + root

// ftg_h smem: A half[128][136] + B half[128][136]; Ch f32[64][132] overlays B
#define SMH_A_BYTES (128 * 136 * 2)     // 34816
#define SMH_TOTAL   (2 * SMH_A_BYTES)   // 69632
#define CH_STRIDE   132

// ---------------- device scratch ----------------
__device__ __half g_xh[Nn * Dd];          // node features, fp16
__device__ float  g_acc[Nn * Dd];         // conv accumulator (fp32), zeroed between layers
__device__ __half g_Wh[SLOTS * Dd * Dd];  // weights TRANSPOSED [slot][n][k], fp16
__device__ int    g_icnt[Rr * Nn];
__device__ float  g_hsel[NSEL * Dd];
__device__ int    g_bcnt[NBKT];
__device__ int    g_bcur[NBKT];
__device__ int    g_boff[NBKT + 1];
__device__ int    g_bsrc[Ee];
__device__ int    g_bdst[Ee];
__device__ float  g_bw[Ee];

// ---------------- helpers ----------------
__device__ __forceinline__ unsigned f2tf(float f) {
    unsigned u;
    asm("cvt.rna.tf32.f32 %0, %1;" : "=r"(u) : "f"(f));
    return u;
}

__device__ __forceinline__ void mma_tf32(float c[4], const unsigned a[4], const unsigned b[2]) {
    asm volatile("mma.sync.aligned.m16n8k8.row.col.f32.tf32.tf32.f32 "
                 "{%0,%1,%2,%3}, {%4,%5,%6,%7}, {%8,%9}, {%0,%1,%2,%3};"
                 : "+f"(c[0]), "+f"(c[1]), "+f"(c[2]), "+f"(c[3])
                 : "r"(a[0]), "r"(a[1]), "r"(a[2]), "r"(a[3]), "r"(b[0]), "r"(b[1]));
}

__device__ __forceinline__ void mma_f16(float c[4], unsigned a0, unsigned a1,
                                        unsigned a2, unsigned a3,
                                        unsigned b0, unsigned b1) {
    asm volatile("mma.sync.aligned.m16n8k16.row.col.f32.f16.f16.f32 "
                 "{%0,%1,%2,%3}, {%4,%5,%6,%7}, {%8,%9}, {%0,%1,%2,%3};"
                 : "+f"(c[0]), "+f"(c[1]), "+f"(c[2]), "+f"(c[3])
                 : "r"(a0), "r"(a1), "r"(a2), "r"(a3), "r"(b0), "r"(b1));
}

__device__ __forceinline__ void cp16(void* smem, const void* g, int srcsize) {
    unsigned a = (unsigned)__cvta_generic_to_shared(smem);
    asm volatile("cp.async.ca.shared.global [%0], [%1], 16, %2;"
                 :: "r"(a), "l"(g), "r"(srcsize));
}

__device__ __forceinline__ void ldsm4(unsigned& r0, unsigned& r1, unsigned& r2, unsigned& r3,
                                      uint32_t addr) {
    asm volatile("ldmatrix.sync.aligned.m8n8.x4.shared.b16 {%0,%1,%2,%3}, [%4];"
                 : "=r"(r0), "=r"(r1), "=r"(r2), "=r"(r3) : "r"(addr));
}

__device__ __forceinline__ uint32_t sma(const void* p) {
    return (uint32_t)__cvta_generic_to_shared(p);
}

// ---------------- small kernels ----------------
// copies fallback rows >= 45000 (rows < 45000 are overwritten by projections),
// zeroes acc for layer 1, zeroes all counters.
__global__ void k_copy_x(const float* __restrict__ src) {
    int i = blockIdx.x * blockDim.x + threadIdx.x;
    if (i >= Nn * Dd / 4) return;
    if (i >= 45000 * 32) {
        float4 v = ((const float4*)src)[i];
        __half2 p0 = __halves2half2(__float2half_rn(v.x), __float2half_rn(v.y));
        __half2 p1 = __halves2half2(__float2half_rn(v.z), __float2half_rn(v.w));
        ((uint2*)g_xh)[i] = make_uint2(*(unsigned*)&p0, *(unsigned*)&p1);
    }
    ((float4*)g_acc)[i] = make_float4(0.f, 0.f, 0.f, 0.f);
    if (i < Rr * Nn) g_icnt[i] = 0;
    if (i < NBKT) { g_bcnt[i] = 0; g_bcur[i] = 0; }
}

// builds W TRANSPOSED into fp16: g_Wh[slot][n][k]
__global__ void k_build_W(const float* __restrict__ comp,
                          const float* __restrict__ bases,
                          const float* __restrict__ root) {
    int i = blockIdx.x * blockDim.x + threadIdx.x;
    if (i >= SLOTS * Dd * Dd) return;
    int slot = i >> 14;
    int idx  = i & 16383;          // n*128 + k
    int n = idx >> 7, k = idx & 127;
    int src = k * 128 + n;         // [k][n] orientation in inputs
    float v;
    if (slot < Rr) {
        v = 0.f;
#pragma unroll
        for (int b = 0; b < 4; b++)
            v += comp[slot * 4 + b] * bases[b * Dd * Dd + src];
    } else {
        v = root[src];
    }
    g_Wh[i] = __float2half_rn(v);
}

__global__ void k_count(const int* __restrict__ ei, const int* __restrict__ et) {
    int e = blockIdx.x * blockDim.x + threadIdx.x;
    if (e >= Ee) return;
    int r = et[e];
    atomicAdd(&g_icnt[r * Nn + ei[Ee + e]], 1);
    atomicAdd(&g_bcnt[r * NG + (ei[e] >> 6)], 1);
}

__global__ void k_scan() {
    __shared__ int part[1024];
    int t = threadIdx.x;
    int s = 0;
#pragma unroll
    for (int j = 0; j < 8; j++) {
        int b = t * 8 + j;
        if (b < NBKT) s += g_bcnt[b];
    }
    part[t] = s;
    __syncthreads();
    for (int o = 1; o < 1024; o <<= 1) {
        int v = (t >= o) ? part[t - o] : 0;
        __syncthreads();
        part[t] += v;
        __syncthreads();
    }
    int run = (t > 0) ? part[t - 1] : 0;
#pragma unroll
    for (int j = 0; j < 8; j++) {
        int b = t * 8 + j;
        if (b < NBKT) { g_boff[b] = run; run += g_bcnt[b]; }
    }
    if (t == 0) g_boff[NBKT] = part[1023];
}

// places edges AND computes the mean weight inline (g_icnt is final after k_count)
__global__ void k_place(const int* __restrict__ ei, const int* __restrict__ et) {
    int e = blockIdx.x * blockDim.x + threadIdx.x;
    if (e >= Ee) return;
    int r = et[e];
    int s = ei[e], t = ei[Ee + e];
    int key = r * NG + (s >> 6);
    int pos = g_boff[key] + atomicAdd(&g_bcur[key], 1);
    g_bsrc[pos] = s;
    g_bdst[pos] = t;
    g_bw[pos]   = 1.0f / fmaxf((float)g_icnt[r * Nn + t], 1.0f);
}

// one warp per node: LayerNorm (+optional ReLU) -> g_xh (fp16); zeroes acc
__global__ void k_ln(const float* __restrict__ g, const float* __restrict__ b, int relu) {
    int gt = blockIdx.x * blockDim.x + threadIdx.x;
    int node = gt >> 5;
    if (node >= Nn) return;
    int lane = gt & 31;
    float4 v = ((const float4*)g_acc)[node * 32 + lane];
    float s = v.x + v.y + v.z + v.w;
    float q = v.x * v.x + v.y * v.y + v.z * v.z + v.w * v.w;
#pragma unroll
    for (int o = 16; o; o >>= 1) {
        s += __shfl_xor_sync(0xffffffffu, s, o);
        q += __shfl_xor_sync(0xffffffffu, q, o);
    }
    float mean = s * (1.f / 128.f);
    float var  = q * (1.f / 128.f) - mean * mean;
    float rstd = rsqrtf(var + 1e-5f);
    float4 gg = ((const float4*)g)[lane];
    float4 bb = ((const float4*)b)[lane];
    float4 o4;
    o4.x = (v.x - mean) * rstd * gg.x + bb.x;
    o4.y = (v.y - mean) * rstd * gg.y + bb.y;
    o4.z = (v.z - mean) * rstd * gg.z + bb.z;
    o4.w = (v.w - mean) * rstd * gg.w + bb.w;
    if (relu) {
        o4.x = fmaxf(o4.x, 0.f); o4.y = fmaxf(o4.y, 0.f);
        o4.z = fmaxf(o4.z, 0.f); o4.w = fmaxf(o4.w, 0.f);
    }
    __half2 p0 = __halves2half2(__float2half_rn(o4.x), __float2half_rn(o4.y));
    __half2 p1 = __halves2half2(__float2half_rn(o4.z), __float2half_rn(o4.w));
    ((uint2*)g_xh)[node * 32 + lane] = make_uint2(*(unsigned*)&p0, *(unsigned*)&p1);
    ((float4*)g_acc)[node * 32 + lane] = make_float4(0.f, 0.f, 0.f, 0.f);
}

__global__ void k_final(const float* __restrict__ W, const float* __restrict__ b,
                        float* __restrict__ out) {
    int gt = blockIdx.x * blockDim.x + threadIdx.x;
    if (gt >= NSEL * NCc) return;
    int i = gt / NCc, c = gt % NCc;
    const float* hr = g_hsel + i * Dd;
    float s = b[c];
#pragma unroll 8
    for (int k = 0; k < Dd; k++) s += hr[k] * W[k * NCc + c];
    out[gt] = s;
}

// ---------------- fused projection GEMM (3 segments, one launch) ----------------
__global__ void __launch_bounds__(256)
proj(const float* A0, const float* W0, const float* b0, const int* x0, int M0, int K0,
     const float* A1, const float* W1, const float* b1, const int* x1, int M1, int K1,
     const float* A2, const float* W2, const float* b2, const int* x2, int M2, int K2,
     int nb0, int nb1) {
    int b = blockIdx.x;
    const float *A, *B, *bias;
    const int* rowIdx;
    int M, K, row0;
    if (b < nb0)            { A = A0; B = W0; bias = b0; rowIdx = x0; M = M0; K = K0; row0 = b * 128; }
    else if (b < nb0 + nb1) { A = A1; B = W1; bias = b1; rowIdx = x1; M = M1; K = K1; row0 = (b - nb0) * 128; }
    else                    { A = A2; B = W2; bias = b2; rowIdx = x2; M = M2; K = K2; row0 = (b - nb0 - nb1) * 128; }

    __shared__ unsigned As[128][36];
    __shared__ unsigned Bs[32][136];
    float acc[2][8][4];
#pragma unroll
    for (int mt = 0; mt < 2; mt++)
#pragma unroll
        for (int nt = 0; nt < 8; nt++)
#pragma unroll
            for (int q = 0; q < 4; q++) acc[mt][nt][q] = 0.f;

    int tid = threadIdx.x;
    int lane = tid & 31, wid = tid >> 5;
    int wm = (wid >> 1) * 32;
    int wn = (wid & 1) * 64;

    for (int kb = 0; kb < K; kb += 32) {
#pragma unroll
        for (int it = 0; it < 4; it++) {
            int idx = tid + it * 256;
            int m = idx >> 3;
            int kq = (idx & 7) * 4;
            float4 v = make_float4(0.f, 0.f, 0.f, 0.f);
            int row = row0 + m;
            if (row < M) v = *(const float4*)&A[(size_t)row * K + kb + kq];
            As[m][kq + 0] = f2tf(v.x); As[m][kq + 1] = f2tf(v.y);
            As[m][kq + 2] = f2tf(v.z); As[m][kq + 3] = f2tf(v.w);
        }
#pragma unroll
        for (int it = 0; it < 4; it++) {
            int idx = tid + it * 256;
            int k = idx >> 5;
            int nq = (idx & 31) * 4;
            float4 v = *(const float4*)&B[(size_t)(kb + k) * 128 + nq];
            Bs[k][nq + 0] = f2tf(v.x); Bs[k][nq + 1] = f2tf(v.y);
            Bs[k][nq + 2] = f2tf(v.z); Bs[k][nq + 3] = f2tf(v.w);
        }
        __syncthreads();
#pragma unroll
        for (int ks = 0; ks < 4; ks++) {
            int k0 = ks * 8;
            unsigned af[2][4];
#pragma unroll
            for (int mt = 0; mt < 2; mt++) {
                int r = wm + mt * 16 + (lane >> 2);
                int c = k0 + (lane & 3);
                af[mt][0] = As[r][c];     af[mt][1] = As[r + 8][c];
                af[mt][2] = As[r][c + 4]; af[mt][3] = As[r + 8][c + 4];
            }
#pragma unroll
            for (int nt = 0; nt < 8; nt++) {
                unsigned bf[2];
                int br = k0 + (lane & 3);
                int bc = wn + nt * 8 + (lane >> 2);
                bf[0] = Bs[br][bc];
                bf[1] = Bs[br + 4][bc];
                mma_tf32(acc[0][nt], af[0], bf);
                mma_tf32(acc[1][nt], af[1], bf);
            }
        }
        __syncthreads();
    }

#pragma unroll
    for (int mt = 0; mt < 2; mt++) {
#pragma unroll
        for (int h = 0; h < 2; h++) {
            int row = row0 + wm + mt * 16 + (lane >> 2) + h * 8;
            if (row >= M) continue;
            int cr = rowIdx[row];
#pragma unroll
            for (int nt = 0; nt < 8; nt++) {
                int col = wn + nt * 8 + 2 * (lane & 3);
                float v0 = acc[mt][nt][h * 2 + 0] + bias[col];
                float v1 = acc[mt][nt][h * 2 + 1] + bias[col + 1];
                __half2 p = __halves2half2(__float2half_rn(v0), __float2half_rn(v1));
                *(unsigned*)&g_xh[(size_t)cr * 128 + col] = *(unsigned*)&p;
            }
        }
    }
}

// ---------------- classifier GEMM: half input (exact cvt), tf32 math, f32 out ----
__global__ void __launch_bounds__(256)
cgemm(const int* __restrict__ aIdx, const float* __restrict__ B,
      const float* __restrict__ bias) {
    int row0 = blockIdx.x * 128;
    __shared__ unsigned As[128][36];
    __shared__ unsigned Bs[32][136];
    float acc[2][8][4];
#pragma unroll
    for (int mt = 0; mt < 2; mt++)
#pragma unroll
        for (int nt = 0; nt < 8; nt++)
#pragma unroll
            for (int q = 0; q < 4; q++) acc[mt][nt][q] = 0.f;

    int tid = threadIdx.x;
    int lane = tid & 31, wid = tid >> 5;
    int wm = (wid >> 1) * 32;
    int wn = (wid & 1) * 64;

    for (int kb = 0; kb < 128; kb += 32) {
#pragma unroll
        for (int it = 0; it < 4; it++) {
            int idx = tid + it * 256;
            int m = idx >> 3;
            int kq = (idx & 7) * 4;
            int row = row0 + m;
            int ar = aIdx[row];
            const __half* src = &g_xh[(size_t)ar * 128 + kb + kq];
            As[m][kq + 0] = f2tf(__half2float(src[0]));
            As[m][kq + 1] = f2tf(__half2float(src[1]));
            As[m][kq + 2] = f2tf(__half2float(src[2]));
            As[m][kq + 3] = f2tf(__half2float(src[3]));
        }
#pragma unroll
        for (int it = 0; it < 4; it++) {
            int idx = tid + it * 256;
            int k = idx >> 5;
            int nq = (idx & 31) * 4;
            float4 v = *(const float4*)&B[(size_t)(kb + k) * 128 + nq];
            Bs[k][nq + 0] = f2tf(v.x); Bs[k][nq + 1] = f2tf(v.y);
            Bs[k][nq + 2] = f2tf(v.z); Bs[k][nq + 3] = f2tf(v.w);
        }
        __syncthreads();
#pragma unroll
        for (int ks = 0; ks < 4; ks++) {
            int k0 = ks * 8;
            unsigned af[2][4];
#pragma unroll
            for (int mt = 0; mt < 2; mt++) {
                int r = wm + mt * 16 + (lane >> 2);
                int c = k0 + (lane & 3);
                af[mt][0] = As[r][c];     af[mt][1] = As[r + 8][c];
                af[mt][2] = As[r][c + 4]; af[mt][3] = As[r + 8][c + 4];
            }
#pragma unroll
            for (int nt = 0; nt < 8; nt++) {
                unsigned bf[2];
                int br = k0 + (lane & 3);
                int bc = wn + nt * 8 + (lane >> 2);
                bf[0] = Bs[br][bc];
                bf[1] = Bs[br + 4][bc];
                mma_tf32(acc[0][nt], af[0], bf);
                mma_tf32(acc[1][nt], af[1], bf);
            }
        }
        __syncthreads();
    }

#pragma unroll
    for (int mt = 0; mt < 2; mt++) {
#pragma unroll
        for (int h = 0; h < 2; h++) {
            int row = row0 + wm + mt * 16 + (lane >> 2) + h * 8;
#pragma unroll
            for (int nt = 0; nt < 8; nt++) {
                int col = wn + nt * 8 + 2 * (lane & 3);
                float v0 = fmaxf(acc[mt][nt][h * 2 + 0] + bias[col], 0.f);
                float v1 = fmaxf(acc[mt][nt][h * 2 + 1] + bias[col + 1], 0.f);
                *(float2*)&g_hsel[(size_t)row * 128 + col] = make_float2(v0, v1);
            }
        }
    }
}

// ---------------- fp16 fused dense GEMM + edge scatter (ldmatrix mainloop) --------
__global__ void __launch_bounds__(256, 2)
ftg_h(const float* __restrict__ bias) {
    extern __shared__ __align__(16) char dsm[];
    __half (*As)[136] = (__half(*)[136])dsm;
    __half (*Bs)[136] = (__half(*)[136])(dsm + SMH_A_BYTES);
    float  (*Ch)[CH_STRIDE] = (float(*)[CH_STRIDE])(dsm + SMH_A_BYTES);  // overlays Bs

    int tile = blockIdx.x;
    int r    = blockIdx.y;
    int row0 = tile * 128;
    bool isRoot = (r == Rr);

    int bkt0 = 0;
    if (!isRoot) {
        bkt0 = r * NG + tile * 2;
        if (g_boff[bkt0] == g_boff[bkt0 + 2]) return;
    }

    int tid = threadIdx.x;
    int lane = tid & 31, wid = tid >> 5;
    int wm = (wid >> 1) * 32;
    int wn = (wid & 1) * 64;

    const __half* Wz = g_Wh + (size_t)r * (Dd * Dd);

#pragma unroll
    for (int it = 0; it < 8; it++) {
        int idx = tid + it * 256;
        int m = idx >> 4, c8 = (idx & 15) * 8;
        int gr = row0 + m;
        cp16(&As[m][c8], &g_xh[(size_t)gr * 128 + c8], gr < Nn ? 16 : 0);
    }
#pragma unroll
    for (int it = 0; it < 8; it++) {
        int idx = tid + it * 256;
        int n = idx >> 4, c8 = (idx & 15) * 8;
        cp16(&Bs[n][c8], &Wz[(size_t)n * 128 + c8], 16);
    }
    asm volatile("cp.async.commit_group;");

    float acc[2][8][4];
#pragma unroll
    for (int mt = 0; mt < 2; mt++)
#pragma unroll
        for (int nt = 0; nt < 8; nt++)
#pragma unroll
            for (int q = 0; q < 4; q++) acc[mt][nt][q] = 0.f;

    // ldmatrix base addresses (per-warp, k advances by 32B per k-step)
    int l7 = lane & 7, lm = (lane >> 3) & 1, lh = lane >> 4;
    uint32_t aAddr[2], bAddr[4];
#pragma unroll
    for (int mt = 0; mt < 2; mt++)
        aAddr[mt] = sma(&As[wm + mt * 16 + lm * 8 + l7][lh * 8]);
#pragma unroll
    for (int p = 0; p < 4; p++)
        bAddr[p] = sma(&Bs[wn + (2 * p + lh) * 8 + l7][lm * 8]);

    asm volatile("cp.async.wait_group 0;" ::: "memory");
    __syncthreads();

#pragma unroll
    for (int ks = 0; ks < 8; ks++) {
        uint32_t off = ks * 32;   // 16 halves per k-step
        unsigned a0[4], a1[4];
        ldsm4(a0[0], a0[1], a0[2], a0[3], aAddr[0] + off);
        ldsm4(a1[0], a1[1], a1[2], a1[3], aAddr[1] + off);
#pragma unroll
        for (int p = 0; p < 4; p++) {
            unsigned b0, b1, b2, b3;
            ldsm4(b0, b1, b2, b3, bAddr[p] + off);
            mma_f16(acc[0][2 * p + 0], a0[0], a0[1], a0[2], a0[3], b0, b1);
            mma_f16(acc[0][2 * p + 1], a0[0], a0[1], a0[2], a0[3], b2, b3);
            mma_f16(acc[1][2 * p + 0], a1[0], a1[1], a1[2], a1[3], b0, b1);
            mma_f16(acc[1][2 * p + 1], a1[0], a1[1], a1[2], a1[3], b2, b3);
        }
    }
    __syncthreads();   // all warps done reading Bs before Ch overlay

    if (isRoot) {
#pragma unroll
        for (int mt = 0; mt < 2; mt++)
#pragma unroll
            for (int h = 0; h < 2; h++) {
                int row = row0 + wm + mt * 16 + (lane >> 2) + h * 8;
                if (row >= Nn) continue;
                float* outr = g_acc + (size_t)row * 128;
#pragma unroll
                for (int nt = 0; nt < 8; nt++) {
                    int col = wn + nt * 8 + 2 * (lane & 3);
                    float v0 = acc[mt][nt][h * 2 + 0] + bias[col];
                    float v1 = acc[mt][nt][h * 2 + 1] + bias[col + 1];
                    asm volatile("red.global.add.v2.f32 [%0], {%1,%2};"
                                 :: "l"(outr + col), "f"(v0), "f"(v1) : "memory");
                }
            }
        return;
    }

    // two-phase: stage 64 rows into Ch, scatter that half's bucket (pipelined)
#pragma unroll
    for (int h2 = 0; h2 < 2; h2++) {
        if ((wm < 64) == (h2 == 0)) {
            int rbase = wm - h2 * 64;
#pragma unroll
            for (int mt = 0; mt < 2; mt++)
#pragma unroll
                for (int h = 0; h < 2; h++) {
                    int rl = rbase + mt * 16 + h * 8 + (lane >> 2);
#pragma unroll
                    for (int nt = 0; nt < 8; nt++) {
                        int col = wn + nt * 8 + 2 * (lane & 3);
                        *(float2*)&Ch[rl][col] =
                            make_float2(acc[mt][nt][h * 2 + 0], acc[mt][nt][h * 2 + 1]);
                    }
                }
        }
        __syncthreads();

        int bkt = bkt0 + h2;
        int lo = g_boff[bkt], hi = g_boff[bkt + 1];
        int i = lo + wid;
        int nsrc = 0, ndst = 0;
        float nw = 0.f;
        if (i < hi) { nsrc = g_bsrc[i]; ndst = g_bdst[i]; nw = g_bw[i]; }
        while (i < hi) {
            int sloc = nsrc & 63;
            int dst  = ndst;
            float w  = nw;
            int inext = i + 8;
            if (inext < hi) { nsrc = g_bsrc[inext]; ndst = g_bdst[inext]; nw = g_bw[inext]; }
            float4 v = *(const float4*)&Ch[sloc][lane * 4];
            v.x *= w; v.y *= w; v.z *= w; v.w *= w;
            float* p = g_acc + (size_t)dst * 128 + lane * 4;
            asm volatile("red.global.add.v4.f32 [%0], {%1,%2,%3,%4};"
                         :: "l"(p), "f"(v.x), "f"(v.y), "f"(v.z), "f"(v.w) : "memory");
            i = inext;
        }
        __syncthreads();
    }
}

// ---------------- launch ----------------
extern "C" void kernel_launch(void* const* d_in, const int* in_sizes, int n_in,
                              void* d_out, int out_size) {
    const int*   edge_index   = (const int*)d_in[0];
    const int*   edge_type    = (const int*)d_in[1];
    const int*   node_indices = (const int*)d_in[2];
    const float* file_feats   = (const float*)d_in[3];
    const int*   file_idx     = (const int*)d_in[4];
    const float* domain_feats = (const float*)d_in[5];
    const int*   domain_idx   = (const int*)d_in[6];
    const float* ip_feats     = (const float*)d_in[7];
    const int*   ip_idx       = (const int*)d_in[8];
    const float* fallback     = (const float*)d_in[9];
    const float* Wf  = (const float*)d_in[10];
    const float* bf  = (const float*)d_in[11];
    const float* Wd  = (const float*)d_in[12];
    const float* bd  = (const float*)d_in[13];
    const float* Wi  = (const float*)d_in[14];
    const float* bi  = (const float*)d_in[15];
    const float* comp1  = (const float*)d_in[16];
    const float* bases1 = (const float*)d_in[17];
    const float* root1  = (const float*)d_in[18];
    const float* bias1  = (const float*)d_in[19];
    const float* comp2  = (const float*)d_in[20];
    const float* bases2 = (const float*)d_in[21];
    const float* root2  = (const float*)d_in[22];
    const float* bias2  = (const float*)d_in[23];
    const float* ln1_g  = (const float*)d_in[24];
    const float* ln1_b  = (const float*)d_in[25];
    const float* ln2_g  = (const float*)d_in[26];
    const float* ln2_b  = (const float*)d_in[27];
    const float* Wc1 = (const float*)d_in[28];
    const float* bc1 = (const float*)d_in[29];
    const float* Wc2 = (const float*)d_in[30];
    const float* bc2 = (const float*)d_in[31];
    float* out = (float*)d_out;

    static int smem_set = 0;
    if (!smem_set) {
        cudaFuncSetAttribute(ftg_h, cudaFuncAttributeMaxDynamicSharedMemorySize, SMH_TOTAL);
        smem_set = 1;
    }

    // ---- node features + zero acc/counters ----
    k_copy_x<<<(Nn * Dd / 4 + 255) / 256, 256>>>(fallback);
    int nb0 = 157, nb1 = 118, nb2 = 79;
    proj<<<nb0 + nb1 + nb2, 256>>>(file_feats,   Wf, bf, file_idx,   20000, 256,
                                   domain_feats, Wd, bd, domain_idx, 15000, 128,
                                   ip_feats,     Wi, bi, ip_idx,     10000, 64,
                                   nb0, nb1);

    // ---- edge counts + bucket sort by (relation, src/64) ----
    k_count<<<(Ee + 255) / 256, 256>>>(edge_index, edge_type);
    k_scan<<<1, 1024>>>();
    k_place<<<(Ee + 255) / 256, 256>>>(edge_index, edge_type);

    dim3 fgrid(NTILE, SLOTS);

    // ---- layer 1 ----
    k_build_W<<<(SLOTS * Dd * Dd + 255) / 256, 256>>>(comp1, bases1, root1);
    ftg_h<<<fgrid, 256, SMH_TOTAL>>>(bias1);
    k_ln<<<(Nn * 32 + 255) / 256, 256>>>(ln1_g, ln1_b, 1);

    // ---- layer 2 ----
    k_build_W<<<(SLOTS * Dd * Dd + 255) / 256, 256>>>(comp2, bases2, root2);
    ftg_h<<<fgrid, 256, SMH_TOTAL>>>(bias2);
    k_ln<<<(Nn * 32 + 255) / 256, 256>>>(ln2_g, ln2_b, 0);

    // ---- classifier ----
    cgemm<<<NSEL / 128, 256>>>(node_indices, Wc1, bc1);
    k_final<<<(NSEL * NCc + 255) / 256, 256>>>(Wc2, bc2, out);
}

// round 12
// speedup vs baseline: 2.2610x; 1.0535x over previous
#include <cuda_runtime.h>
#include <cuda_fp16.h>
#include <cstdint>

// Problem constants
#define Nn    50000
#define Dd    128
#define Rr    10
#define Ee    800000
#define NSEL  8192
#define NCc   12
#define NTILE 391                 // ceil(Nn/128)
#define NG    782                 // ceil(Nn/64) src groups
#define NBKT  (Rr * NG)
#define SLOTS (Rr + 1)            // 10 relations + root

// ftg_h smem: A half[128][136] + B half[128][136]; Ch f32[128][132] overlays A+B
#define SMH_A_BYTES (128 * 136 * 2)     // 34816
#define SMH_TOTAL   (2 * SMH_A_BYTES)   // 69632  (Ch needs 67584 <= this)
#define CH_STRIDE   132

// mega-kernel block ranges
#define NB_PROJ  354      // 157 + 118 + 79
#define NB_COPY  6250     // Nn*Dd/4 / 256 = 1,600,000 / 256
#define NB_CNT   3125     // Ee / 256

// ---------------- device scratch ----------------
__device__ __half g_xh[Nn * Dd];              // node features, fp16
__device__ float  g_acc[Nn * Dd];             // conv accumulator (fp32)
__device__ __half g_Wh[2 * SLOTS * Dd * Dd];  // both layers' W^T [layer][slot][n][k]
__device__ int    g_icnt[Rr * Nn];
__device__ float  g_hsel[NSEL * Dd];
__device__ int    g_bcnt[NBKT];
__device__ int    g_bcur[NBKT];
__device__ int    g_boff[NBKT + 1];
__device__ int    g_bsrc[Ee];
__device__ int    g_bdst[Ee];
__device__ float  g_bw[Ee];

// ---------------- helpers ----------------
__device__ __forceinline__ unsigned f2tf(float f) {
    unsigned u;
    asm("cvt.rna.tf32.f32 %0, %1;" : "=r"(u) : "f"(f));
    return u;
}

__device__ __forceinline__ void mma_tf32(float c[4], const unsigned a[4], const unsigned b[2]) {
    asm volatile("mma.sync.aligned.m16n8k8.row.col.f32.tf32.tf32.f32 "
                 "{%0,%1,%2,%3}, {%4,%5,%6,%7}, {%8,%9}, {%0,%1,%2,%3};"
                 : "+f"(c[0]), "+f"(c[1]), "+f"(c[2]), "+f"(c[3])
                 : "r"(a[0]), "r"(a[1]), "r"(a[2]), "r"(a[3]), "r"(b[0]), "r"(b[1]));
}

__device__ __forceinline__ void mma_f16(float c[4], unsigned a0, unsigned a1,
                                        unsigned a2, unsigned a3,
                                        unsigned b0, unsigned b1) {
    asm volatile("mma.sync.aligned.m16n8k16.row.col.f32.f16.f16.f32 "
                 "{%0,%1,%2,%3}, {%4,%5,%6,%7}, {%8,%9}, {%0,%1,%2,%3};"
                 : "+f"(c[0]), "+f"(c[1]), "+f"(c[2]), "+f"(c[3])
                 : "r"(a0), "r"(a1), "r"(a2), "r"(a3), "r"(b0), "r"(b1));
}

__device__ __forceinline__ void cp16(void* smem, const void* g, int srcsize) {
    unsigned a = (unsigned)__cvta_generic_to_shared(smem);
    asm volatile("cp.async.ca.shared.global [%0], [%1], 16, %2;"
                 :: "r"(a), "l"(g), "r"(srcsize));
}

__device__ __forceinline__ void ldsm4(unsigned& r0, unsigned& r1, unsigned& r2, unsigned& r3,
                                      uint32_t addr) {
    asm volatile("ldmatrix.sync.aligned.m8n8.x4.shared.b16 {%0,%1,%2,%3}, [%4];"
                 : "=r"(r0), "=r"(r1), "=r"(r2), "=r"(r3) : "r"(addr));
}

__device__ __forceinline__ uint32_t sma(const void* p) {
    return (uint32_t)__cvta_generic_to_shared(p);
}

// ---------------- small kernels ----------------
__global__ void k_zero() {
    int i = blockIdx.x * blockDim.x + threadIdx.x;
    if (i < Rr * Nn) g_icnt[i] = 0;
    if (i < NBKT) { g_bcnt[i] = 0; g_bcur[i] = 0; }
}

// builds both layers' W TRANSPOSED into fp16: g_Wh[layer][slot][n][k]
__global__ void k_build_W2(const float* __restrict__ comp1, const float* __restrict__ bases1,
                           const float* __restrict__ root1,
                           const float* __restrict__ comp2, const float* __restrict__ bases2,
                           const float* __restrict__ root2) {
    int i = blockIdx.x * blockDim.x + threadIdx.x;
    if (i >= SLOTS * Dd * Dd) return;
    int layer = blockIdx.y;
    const float* comp  = layer ? comp2  : comp1;
    const float* bases = layer ? bases2 : bases1;
    const float* root  = layer ? root2  : root1;
    int slot = i >> 14;
    int idx  = i & 16383;          // n*128 + k
    int n = idx >> 7, k = idx & 127;
    int src = k * 128 + n;
    float v;
    if (slot < Rr) {
        v = 0.f;
#pragma unroll
        for (int b = 0; b < 4; b++)
            v += comp[slot * 4 + b] * bases[b * Dd * Dd + src];
    } else {
        v = root[src];
    }
    g_Wh[layer * SLOTS * Dd * Dd + i] = __float2half_rn(v);
}

// warp-shuffle two-level scan over NBKT bucket counts -> g_boff
__global__ void k_scan() {
    __shared__ int wsum[32];
    int t = threadIdx.x;
    int lane = t & 31, wid = t >> 5;
    int cnt[8];
    int s = 0;
#pragma unroll
    for (int j = 0; j < 8; j++) {
        int b = t * 8 + j;
        cnt[j] = (b < NBKT) ? g_bcnt[b] : 0;
        s += cnt[j];
    }
    int incl = s;
#pragma unroll
    for (int o = 1; o < 32; o <<= 1) {
        int v = __shfl_up_sync(0xffffffffu, incl, o);
        if (lane >= o) incl += v;
    }
    if (lane == 31) wsum[wid] = incl;
    __syncthreads();
    if (wid == 0) {
        int v = wsum[lane];
        int iv = v;
#pragma unroll
        for (int o = 1; o < 32; o <<= 1) {
            int u = __shfl_up_sync(0xffffffffu, iv, o);
            if (lane >= o) iv += u;
        }
        wsum[lane] = iv - v;   // exclusive warp offsets
        if (lane == 31) g_boff[NBKT] = iv;
    }
    __syncthreads();
    int run = wsum[wid] + (incl - s);
#pragma unroll
    for (int j = 0; j < 8; j++) {
        int b = t * 8 + j;
        if (b < NBKT) { g_boff[b] = run; run += cnt[j]; }
    }
}

// places edges AND computes the mean weight inline
__global__ void k_place(const int* __restrict__ ei, const int* __restrict__ et) {
    int e = blockIdx.x * blockDim.x + threadIdx.x;
    if (e >= Ee) return;
    int r = et[e];
    int s = ei[e], t = ei[Ee + e];
    int key = r * NG + (s >> 6);
    int pos = g_boff[key] + atomicAdd(&g_bcur[key], 1);
    g_bsrc[pos] = s;
    g_bdst[pos] = t;
    g_bw[pos]   = 1.0f / fmaxf((float)g_icnt[r * Nn + t], 1.0f);
}

// one warp per node: LayerNorm (+optional ReLU) -> g_xh (fp16); zeroes acc
__global__ void k_ln(const float* __restrict__ g, const float* __restrict__ b, int relu) {
    int gt = blockIdx.x * blockDim.x + threadIdx.x;
    int node = gt >> 5;
    if (node >= Nn) return;
    int lane = gt & 31;
    float4 v = ((const float4*)g_acc)[node * 32 + lane];
    float s = v.x + v.y + v.z + v.w;
    float q = v.x * v.x + v.y * v.y + v.z * v.z + v.w * v.w;
#pragma unroll
    for (int o = 16; o; o >>= 1) {
        s += __shfl_xor_sync(0xffffffffu, s, o);
        q += __shfl_xor_sync(0xffffffffu, q, o);
    }
    float mean = s * (1.f / 128.f);
    float var  = q * (1.f / 128.f) - mean * mean;
    float rstd = rsqrtf(var + 1e-5f);
    float4 gg = ((const float4*)g)[lane];
    float4 bb = ((const float4*)b)[lane];
    float4 o4;
    o4.x = (v.x - mean) * rstd * gg.x + bb.x;
    o4.y = (v.y - mean) * rstd * gg.y + bb.y;
    o4.z = (v.z - mean) * rstd * gg.z + bb.z;
    o4.w = (v.w - mean) * rstd * gg.w + bb.w;
    if (relu) {
        o4.x = fmaxf(o4.x, 0.f); o4.y = fmaxf(o4.y, 0.f);
        o4.z = fmaxf(o4.z, 0.f); o4.w = fmaxf(o4.w, 0.f);
    }
    __half2 p0 = __halves2half2(__float2half_rn(o4.x), __float2half_rn(o4.y));
    __half2 p1 = __halves2half2(__float2half_rn(o4.z), __float2half_rn(o4.w));
    ((uint2*)g_xh)[node * 32 + lane] = make_uint2(*(unsigned*)&p0, *(unsigned*)&p1);
    ((float4*)g_acc)[node * 32 + lane] = make_float4(0.f, 0.f, 0.f, 0.f);
}

__global__ void k_final(const float* __restrict__ W, const float* __restrict__ b,
                        float* __restrict__ out) {
    int gt = blockIdx.x * blockDim.x + threadIdx.x;
    if (gt >= NSEL * NCc) return;
    int i = gt / NCc, c = gt % NCc;
    const float* hr = g_hsel + i * Dd;
    float s = b[c];
#pragma unroll 8
    for (int k = 0; k < Dd; k++) s += hr[k] * W[k * NCc + c];
    out[gt] = s;
}

// ---------------- mega kernel: proj (3 segs) || fallback-copy+acc-zero || edge-count --
__global__ void __launch_bounds__(256)
k_mega(const float* A0, const float* W0, const float* b0, const int* x0, int M0, int K0,
       const float* A1, const float* W1, const float* b1, const int* x1, int M1, int K1,
       const float* A2, const float* W2, const float* b2, const int* x2, int M2, int K2,
       const float* __restrict__ fallback,
       const int* __restrict__ ei, const int* __restrict__ et) {
    int blk = blockIdx.x;
    int tid = threadIdx.x;

    if (blk >= NB_PROJ) {
        if (blk < NB_PROJ + NB_COPY) {
            // fallback copy (rows >= 45000) + acc zero
            int i = (blk - NB_PROJ) * 256 + tid;
            if (i < Nn * Dd / 4) {
                if (i >= 45000 * 32) {
                    float4 v = ((const float4*)fallback)[i];
                    __half2 p0 = __halves2half2(__float2half_rn(v.x), __float2half_rn(v.y));
                    __half2 p1 = __halves2half2(__float2half_rn(v.z), __float2half_rn(v.w));
                    ((uint2*)g_xh)[i] = make_uint2(*(unsigned*)&p0, *(unsigned*)&p1);
                }
                ((float4*)g_acc)[i] = make_float4(0.f, 0.f, 0.f, 0.f);
            }
        } else {
            // edge count
            int e = (blk - NB_PROJ - NB_COPY) * 256 + tid;
            if (e < Ee) {
                int r = et[e];
                atomicAdd(&g_icnt[r * Nn + ei[Ee + e]], 1);
                atomicAdd(&g_bcnt[r * NG + (ei[e] >> 6)], 1);
            }
        }
        return;
    }

    // ---- projection GEMM segment ----
    const float *A, *B, *bias;
    const int* rowIdx;
    int M, K, row0;
    if (blk < 157)      { A = A0; B = W0; bias = b0; rowIdx = x0; M = M0; K = K0; row0 = blk * 128; }
    else if (blk < 275) { A = A1; B = W1; bias = b1; rowIdx = x1; M = M1; K = K1; row0 = (blk - 157) * 128; }
    else                { A = A2; B = W2; bias = b2; rowIdx = x2; M = M2; K = K2; row0 = (blk - 275) * 128; }

    __shared__ unsigned As[128][36];
    __shared__ unsigned Bs[32][136];
    float acc[2][8][4];
#pragma unroll
    for (int mt = 0; mt < 2; mt++)
#pragma unroll
        for (int nt = 0; nt < 8; nt++)
#pragma unroll
            for (int q = 0; q < 4; q++) acc[mt][nt][q] = 0.f;

    int lane = tid & 31, wid = tid >> 5;
    int wm = (wid >> 1) * 32;
    int wn = (wid & 1) * 64;

    for (int kb = 0; kb < K; kb += 32) {
#pragma unroll
        for (int it = 0; it < 4; it++) {
            int idx = tid + it * 256;
            int m = idx >> 3;
            int kq = (idx & 7) * 4;
            float4 v = make_float4(0.f, 0.f, 0.f, 0.f);
            int row = row0 + m;
            if (row < M) v = *(const float4*)&A[(size_t)row * K + kb + kq];
            As[m][kq + 0] = f2tf(v.x); As[m][kq + 1] = f2tf(v.y);
            As[m][kq + 2] = f2tf(v.z); As[m][kq + 3] = f2tf(v.w);
        }
#pragma unroll
        for (int it = 0; it < 4; it++) {
            int idx = tid + it * 256;
            int k = idx >> 5;
            int nq = (idx & 31) * 4;
            float4 v = *(const float4*)&B[(size_t)(kb + k) * 128 + nq];
            Bs[k][nq + 0] = f2tf(v.x); Bs[k][nq + 1] = f2tf(v.y);
            Bs[k][nq + 2] = f2tf(v.z); Bs[k][nq + 3] = f2tf(v.w);
        }
        __syncthreads();
#pragma unroll
        for (int ks = 0; ks < 4; ks++) {
            int k0 = ks * 8;
            unsigned af[2][4];
#pragma unroll
            for (int mt = 0; mt < 2; mt++) {
                int r = wm + mt * 16 + (lane >> 2);
                int c = k0 + (lane & 3);
                af[mt][0] = As[r][c];     af[mt][1] = As[r + 8][c];
                af[mt][2] = As[r][c + 4]; af[mt][3] = As[r + 8][c + 4];
            }
#pragma unroll
            for (int nt = 0; nt < 8; nt++) {
                unsigned bf[2];
                int br = k0 + (lane & 3);
                int bc = wn + nt * 8 + (lane >> 2);
                bf[0] = Bs[br][bc];
                bf[1] = Bs[br + 4][bc];
                mma_tf32(acc[0][nt], af[0], bf);
                mma_tf32(acc[1][nt], af[1], bf);
            }
        }
        __syncthreads();
    }

#pragma unroll
    for (int mt = 0; mt < 2; mt++) {
#pragma unroll
        for (int h = 0; h < 2; h++) {
            int row = row0 + wm + mt * 16 + (lane >> 2) + h * 8;
            if (row >= M) continue;
            int cr = rowIdx[row];
#pragma unroll
            for (int nt = 0; nt < 8; nt++) {
                int col = wn + nt * 8 + 2 * (lane & 3);
                float v0 = acc[mt][nt][h * 2 + 0] + bias[col];
                float v1 = acc[mt][nt][h * 2 + 1] + bias[col + 1];
                __half2 p = __halves2half2(__float2half_rn(v0), __float2half_rn(v1));
                *(unsigned*)&g_xh[(size_t)cr * 128 + col] = *(unsigned*)&p;
            }
        }
    }
}

// ---------------- classifier GEMM: half input (exact cvt), tf32 math, f32 out ----
__global__ void __launch_bounds__(256)
cgemm(const int* __restrict__ aIdx, const float* __restrict__ B,
      const float* __restrict__ bias) {
    int row0 = blockIdx.x * 128;
    __shared__ unsigned As[128][36];
    __shared__ unsigned Bs[32][136];
    float acc[2][8][4];
#pragma unroll
    for (int mt = 0; mt < 2; mt++)
#pragma unroll
        for (int nt = 0; nt < 8; nt++)
#pragma unroll
            for (int q = 0; q < 4; q++) acc[mt][nt][q] = 0.f;

    int tid = threadIdx.x;
    int lane = tid & 31, wid = tid >> 5;
    int wm = (wid >> 1) * 32;
    int wn = (wid & 1) * 64;

    for (int kb = 0; kb < 128; kb += 32) {
#pragma unroll
        for (int it = 0; it < 4; it++) {
            int idx = tid + it * 256;
            int m = idx >> 3;
            int kq = (idx & 7) * 4;
            int row = row0 + m;
            int ar = aIdx[row];
            const __half* src = &g_xh[(size_t)ar * 128 + kb + kq];
            As[m][kq + 0] = f2tf(__half2float(src[0]));
            As[m][kq + 1] = f2tf(__half2float(src[1]));
            As[m][kq + 2] = f2tf(__half2float(src[2]));
            As[m][kq + 3] = f2tf(__half2float(src[3]));
        }
#pragma unroll
        for (int it = 0; it < 4; it++) {
            int idx = tid + it * 256;
            int k = idx >> 5;
            int nq = (idx & 31) * 4;
            float4 v = *(const float4*)&B[(size_t)(kb + k) * 128 + nq];
            Bs[k][nq + 0] = f2tf(v.x); Bs[k][nq + 1] = f2tf(v.y);
            Bs[k][nq + 2] = f2tf(v.z); Bs[k][nq + 3] = f2tf(v.w);
        }
        __syncthreads();
#pragma unroll
        for (int ks = 0; ks < 4; ks++) {
            int k0 = ks * 8;
            unsigned af[2][4];
#pragma unroll
            for (int mt = 0; mt < 2; mt++) {
                int r = wm + mt * 16 + (lane >> 2);
                int c = k0 + (lane & 3);
                af[mt][0] = As[r][c];     af[mt][1] = As[r + 8][c];
                af[mt][2] = As[r][c + 4]; af[mt][3] = As[r + 8][c + 4];
            }
#pragma unroll
            for (int nt = 0; nt < 8; nt++) {
                unsigned bf[2];
                int br = k0 + (lane & 3);
                int bc = wn + nt * 8 + (lane >> 2);
                bf[0] = Bs[br][bc];
                bf[1] = Bs[br + 4][bc];
                mma_tf32(acc[0][nt], af[0], bf);
                mma_tf32(acc[1][nt], af[1], bf);
            }
        }
        __syncthreads();
    }

#pragma unroll
    for (int mt = 0; mt < 2; mt++) {
#pragma unroll
        for (int h = 0; h < 2; h++) {
            int row = row0 + wm + mt * 16 + (lane >> 2) + h * 8;
#pragma unroll
            for (int nt = 0; nt < 8; nt++) {
                int col = wn + nt * 8 + 2 * (lane & 3);
                float v0 = fmaxf(acc[mt][nt][h * 2 + 0] + bias[col], 0.f);
                float v1 = fmaxf(acc[mt][nt][h * 2 + 1] + bias[col + 1], 0.f);
                *(float2*)&g_hsel[(size_t)row * 128 + col] = make_float2(v0, v1);
            }
        }
    }
}

// ---------------- fp16 fused dense GEMM + edge scatter (single-phase epilogue) ------
__global__ void __launch_bounds__(256, 2)
ftg_h(const float* __restrict__ bias, int layer) {
    extern __shared__ __align__(16) char dsm[];
    __half (*As)[136] = (__half(*)[136])dsm;
    __half (*Bs)[136] = (__half(*)[136])(dsm + SMH_A_BYTES);
    float  (*Ch)[CH_STRIDE] = (float(*)[CH_STRIDE])dsm;   // overlays A+B after MMA

    int tile = blockIdx.x;
    int r    = blockIdx.y;
    int row0 = tile * 128;
    bool isRoot = (r == Rr);

    int bkt0 = 0;
    if (!isRoot) {
        bkt0 = r * NG + tile * 2;
        if (g_boff[bkt0] == g_boff[bkt0 + 2]) return;
    }

    int tid = threadIdx.x;
    int lane = tid & 31, wid = tid >> 5;
    int wm = (wid >> 1) * 32;
    int wn = (wid & 1) * 64;

    const __half* Wz = g_Wh + (size_t)(layer * SLOTS + r) * (Dd * Dd);

#pragma unroll
    for (int it = 0; it < 8; it++) {
        int idx = tid + it * 256;
        int m = idx >> 4, c8 = (idx & 15) * 8;
        int gr = row0 + m;
        cp16(&As[m][c8], &g_xh[(size_t)gr * 128 + c8], gr < Nn ? 16 : 0);
    }
#pragma unroll
    for (int it = 0; it < 8; it++) {
        int idx = tid + it * 256;
        int n = idx >> 4, c8 = (idx & 15) * 8;
        cp16(&Bs[n][c8], &Wz[(size_t)n * 128 + c8], 16);
    }
    asm volatile("cp.async.commit_group;");

    float acc[2][8][4];
#pragma unroll
    for (int mt = 0; mt < 2; mt++)
#pragma unroll
        for (int nt = 0; nt < 8; nt++)
#pragma unroll
            for (int q = 0; q < 4; q++) acc[mt][nt][q] = 0.f;

    // ldmatrix base addresses
    int l7 = lane & 7, lm = (lane >> 3) & 1, lh = lane >> 4;
    uint32_t aAddr[2], bAddr[4];
#pragma unroll
    for (int mt = 0; mt < 2; mt++)
        aAddr[mt] = sma(&As[wm + mt * 16 + lm * 8 + l7][lh * 8]);
#pragma unroll
    for (int p = 0; p < 4; p++)
        bAddr[p] = sma(&Bs[wn + (2 * p + lh) * 8 + l7][lm * 8]);

    asm volatile("cp.async.wait_group 0;" ::: "memory");
    __syncthreads();

#pragma unroll
    for (int ks = 0; ks < 8; ks++) {
        uint32_t off = ks * 32;
        unsigned a0[4], a1[4];
        ldsm4(a0[0], a0[1], a0[2], a0[3], aAddr[0] + off);
        ldsm4(a1[0], a1[1], a1[2], a1[3], aAddr[1] + off);
#pragma unroll
        for (int p = 0; p < 4; p++) {
            unsigned b0, b1, b2, b3;
            ldsm4(b0, b1, b2, b3, bAddr[p] + off);
            mma_f16(acc[0][2 * p + 0], a0[0], a0[1], a0[2], a0[3], b0, b1);
            mma_f16(acc[0][2 * p + 1], a0[0], a0[1], a0[2], a0[3], b2, b3);
            mma_f16(acc[1][2 * p + 0], a1[0], a1[1], a1[2], a1[3], b0, b1);
            mma_f16(acc[1][2 * p + 1], a1[0], a1[1], a1[2], a1[3], b2, b3);
        }
    }

    if (isRoot) {
#pragma unroll
        for (int mt = 0; mt < 2; mt++)
#pragma unroll
            for (int h = 0; h < 2; h++) {
                int row = row0 + wm + mt * 16 + (lane >> 2) + h * 8;
                if (row >= Nn) continue;
                float* outr = g_acc + (size_t)row * 128;
#pragma unroll
                for (int nt = 0; nt < 8; nt++) {
                    int col = wn + nt * 8 + 2 * (lane & 3);
                    float v0 = acc[mt][nt][h * 2 + 0] + bias[col];
                    float v1 = acc[mt][nt][h * 2 + 1] + bias[col + 1];
                    asm volatile("red.global.add.v2.f32 [%0], {%1,%2};"
                                 :: "l"(outr + col), "f"(v0), "f"(v1) : "memory");
                }
            }
        return;
    }

    __syncthreads();   // all warps done with A/B smem (ldmatrix) before Ch overlay

    // stage full 128-row tile into Ch (all 8 warps write their own acc rows)
#pragma unroll
    for (int mt = 0; mt < 2; mt++)
#pragma unroll
        for (int h = 0; h < 2; h++) {
            int rl = wm + mt * 16 + h * 8 + (lane >> 2);
#pragma unroll
            for (int nt = 0; nt < 8; nt++) {
                int col = wn + nt * 8 + 2 * (lane & 3);
                *(float2*)&Ch[rl][col] =
                    make_float2(acc[mt][nt][h * 2 + 0], acc[mt][nt][h * 2 + 1]);
            }
        }
    __syncthreads();

    // single scatter loop over the contiguous bucket pair (pipelined)
    int lo = g_boff[bkt0], hi = g_boff[bkt0 + 2];
    int i = lo + wid;
    int nsrc = 0, ndst = 0;
    float nw = 0.f;
    if (i < hi) { nsrc = g_bsrc[i]; ndst = g_bdst[i]; nw = g_bw[i]; }
    while (i < hi) {
        int sloc = nsrc & 127;
        int dst  = ndst;
        float w  = nw;
        int inext = i + 8;
        if (inext < hi) { nsrc = g_bsrc[inext]; ndst = g_bdst[inext]; nw = g_bw[inext]; }
        float4 v = *(const float4*)&Ch[sloc][lane * 4];
        v.x *= w; v.y *= w; v.z *= w; v.w *= w;
        float* p = g_acc + (size_t)dst * 128 + lane * 4;
        asm volatile("red.global.add.v4.f32 [%0], {%1,%2,%3,%4};"
                     :: "l"(p), "f"(v.x), "f"(v.y), "f"(v.z), "f"(v.w) : "memory");
        i = inext;
    }
}

// ---------------- launch ----------------
extern "C" void kernel_launch(void* const* d_in, const int* in_sizes, int n_in,
                              void* d_out, int out_size) {
    const int*   edge_index   = (const int*)d_in[0];
    const int*   edge_type    = (const int*)d_in[1];
    const int*   node_indices = (const int*)d_in[2];
    const float* file_feats   = (const float*)d_in[3];
    const int*   file_idx     = (const int*)d_in[4];
    const float* domain_feats = (const float*)d_in[5];
    const int*   domain_idx   = (const int*)d_in[6];
    const float* ip_feats     = (const float*)d_in[7];
    const int*   ip_idx       = (const int*)d_in[8];
    const float* fallback     = (const float*)d_in[9];
    const float* Wf  = (const float*)d_in[10];
    const float* bf  = (const float*)d_in[11];
    const float* Wd  = (const float*)d_in[12];
    const float* bd  = (const float*)d_in[13];
    const float* Wi  = (const float*)d_in[14];
    const float* bi  = (const float*)d_in[15];
    const float* comp1  = (const float*)d_in[16];
    const float* bases1 = (const float*)d_in[17];
    const float* root1  = (const float*)d_in[18];
    const float* bias1  = (const float*)d_in[19];
    const float* comp2  = (const float*)d_in[20];
    const float* bases2 = (const float*)d_in[21];
    const float* root2  = (const float*)d_in[22];
    const float* bias2  = (const float*)d_in[23];
    const float* ln1_g  = (const float*)d_in[24];
    const float* ln1_b  = (const float*)d_in[25];
    const float* ln2_g  = (const float*)d_in[26];
    const float* ln2_b  = (const float*)d_in[27];
    const float* Wc1 = (const float*)d_in[28];
    const float* bc1 = (const float*)d_in[29];
    const float* Wc2 = (const float*)d_in[30];
    const float* bc2 = (const float*)d_in[31];
    float* out = (float*)d_out;

    static int smem_set = 0;
    if (!smem_set) {
        cudaFuncSetAttribute(ftg_h, cudaFuncAttributeMaxDynamicSharedMemorySize, SMH_TOTAL);
        smem_set = 1;
    }

    // ---- zero counters, then fused proj || copy/acc-zero || count ----
    k_zero<<<(Rr * Nn + 255) / 256, 256>>>();
    k_mega<<<NB_PROJ + NB_COPY + NB_CNT, 256>>>(
        file_feats,   Wf, bf, file_idx,   20000, 256,
        domain_feats, Wd, bd, domain_idx, 15000, 128,
        ip_feats,     Wi, bi, ip_idx,     10000, 64,
        fallback, edge_index, edge_type);

    // ---- both layers' weights (independent of activations) ----
    k_build_W2<<<dim3((SLOTS * Dd * Dd + 255) / 256, 2), 256>>>(
        comp1, bases1, root1, comp2, bases2, root2);

    // ---- bucket sort finalize ----
    k_scan<<<1, 1024>>>();
    k_place<<<(Ee + 255) / 256, 256>>>(edge_index, edge_type);

    dim3 fgrid(NTILE, SLOTS);

    // ---- layer 1 ----
    ftg_h<<<fgrid, 256, SMH_TOTAL>>>(bias1, 0);
    k_ln<<<(Nn * 32 + 255) / 256, 256>>>(ln1_g, ln1_b, 1);

    // ---- layer 2 ----
    ftg_h<<<fgrid, 256, SMH_TOTAL>>>(bias2, 1);
    k_ln<<<(Nn * 32 + 255) / 256, 256>>>(ln2_g, ln2_b, 0);

    // ---- classifier ----
    cgemm<<<NSEL / 128, 256>>>(node_indices, Wc1, bc1);
    k_final<<<(NSEL * NCc + 255) / 256, 256>>>(Wc2, bc2, out);
}